// round 8
// baseline (speedup 1.0000x reference)
#include <cuda_runtime.h>
#include <math.h>
#include <stdint.h>

#define NMAX 50000
#define EMAX 400000
#define GTE 64       // edges per gemm tile
#define CHUNK 51200  // edges per gemm+scatter chunk (multiple of GTE)

// ---- scratch (device globals; no allocation allowed) ----
__device__ float g_ref_accum[NMAX * 4];   // sum x,y,z + count
__device__ float g_ref_vec[NMAX * 3];
__device__ float g_sproj[(size_t)NMAX * 192];
__device__ float g_geom[(size_t)EMAX * 8];
__device__ float g_x[(size_t)EMAX * 192];  // gated per-edge messages

// ---------------- helpers ----------------
typedef unsigned long long u64;
__device__ __forceinline__ u64 pk2(float lo, float hi) {
    u64 r;
    asm("mov.b64 %0, {%1, %2};" : "=l"(r) : "f"(lo), "f"(hi));
    return r;
}
__device__ __forceinline__ void upk2(u64 v, float& lo, float& hi) {
    asm("mov.b64 {%0, %1}, %2;" : "=f"(lo), "=f"(hi) : "l"(v));
}
__device__ __forceinline__ u64 ffma2(u64 a, u64 b, u64 c) {
    u64 d;
    asm("fma.rn.f32x2 %0, %1, %2, %3;" : "=l"(d) : "l"(a), "l"(b), "l"(c));
    return d;
}
__device__ __forceinline__ float tanh_fast(float x) {
    float y;
    asm("tanh.approx.f32 %0, %1;" : "=f"(y) : "f"(x));
    return y;
}
__device__ __forceinline__ void red4(float* a, float x, float y, float z, float w) {
    asm volatile("red.global.add.v4.f32 [%0], {%1, %2, %3, %4};"
                 :: "l"(a), "f"(x), "f"(y), "f"(z), "f"(w) : "memory");
}
__device__ __forceinline__ uint32_t f2tf32(float v) {
    uint32_t t;
    asm("cvt.rna.tf32.f32 %0, %1;" : "=r"(t) : "f"(v));
    return t;
}
__device__ __forceinline__ void mma_tf32(float c[4], uint32_t a0, uint32_t a1,
                                         uint32_t a2, uint32_t a3,
                                         uint32_t b0, uint32_t b1) {
    asm volatile(
        "mma.sync.aligned.m16n8k8.row.col.f32.tf32.tf32.f32 "
        "{%0,%1,%2,%3}, {%4,%5,%6,%7}, {%8,%9}, {%0,%1,%2,%3};"
        : "+f"(c[0]), "+f"(c[1]), "+f"(c[2]), "+f"(c[3])
        : "r"(a0), "r"(a1), "r"(a2), "r"(a3), "r"(b0), "r"(b1));
}
__device__ __forceinline__ float gatef(float g) {
    float sg = __fdividef(g, 1.0f + __expf(-g)) * (1.0f / 0.6f);
    return 1.0f + tanh_fast(sg);
}

// ================= kernel 1: zero output + accumulators =================
__global__ void k_zero(float4* __restrict__ out4, int n_out4, int n_acc4) {
    float4* acc4 = (float4*)g_ref_accum;
    int total = n_out4 + n_acc4;
    float4 z = make_float4(0.f, 0.f, 0.f, 0.f);
    for (int i = blockIdx.x * blockDim.x + threadIdx.x; i < total;
         i += gridDim.x * blockDim.x) {
        if (i < n_out4) out4[i] = z;
        else acc4[i - n_out4] = z;
    }
}

// ================= kernel 2: segment-sum of edge_udiff over i =================
__global__ void k_refaccum(const float* __restrict__ ud,
                           const int* __restrict__ eidx, int E) {
    int e = blockIdx.x * blockDim.x + threadIdx.x;
    if (e >= E) return;
    int i = eidx[E + e];
    red4(&g_ref_accum[i * 4], ud[e * 3 + 0], ud[e * 3 + 1], ud[e * 3 + 2], 1.0f);
}

// ================= kernel 3: normalize ref vector per node =================
__global__ void k_refvec(int N) {
    int n = blockIdx.x * blockDim.x + threadIdx.x;
    if (n >= N) return;
    float4 a = *(const float4*)&g_ref_accum[n * 4];
    float ic = 1.0f / fmaxf(a.w, 1.0f);
    float rx = a.x * ic, ry = a.y * ic, rz = a.z * ic;
    float norm = sqrtf(rx * rx + ry * ry + rz * rz + 1e-9f);
    float inm = 1.0f / norm;
    rx *= inm; ry *= inm; rz *= inm;
    if (norm < 5e-5f) { rx = 1.0f; ry = 0.0f; rz = 0.0f; }
    g_ref_vec[n * 3 + 0] = rx;
    g_ref_vec[n * 3 + 1] = ry;
    g_ref_vec[n * 3 + 2] = rz;
}

// ================= kernel 4: node scalar MLP projection =================
__global__ void __launch_bounds__(256)
k_sproj(const float* __restrict__ ns, const float* __restrict__ W1,
        const float* __restrict__ b1, const float* __restrict__ W2,
        const float* __restrict__ b2, int N) {
    __shared__ float sW1[64 * 32];
    __shared__ float sW2[32 * 192];
    int tid = threadIdx.x;
    for (int q = tid; q < 64 * 32; q += 256) sW1[q] = W1[q];
    for (int q = tid; q < 32 * 192; q += 256) sW2[q] = W2[q];
    __syncthreads();
    const u64* sW2u = (const u64*)sW2;
    const float2* b2p = (const float2*)b2;
    int lane = tid & 31, warp = tid >> 5;

    u64 bb[3];
#pragma unroll
    for (int k = 0; k < 3; k++) {
        float2 t = b2p[lane + 32 * k];
        bb[k] = pk2(t.x, t.y);
    }
    float b1v = b1[lane];

    int npairs = (N + 1) >> 1;
    for (int p = blockIdx.x * 8 + warp; p < npairs; p += gridDim.x * 8) {
        int nA = p * 2;
        int nB = min(nA + 1, N - 1);
        float aA0 = ns[(size_t)nA * 64 + lane], aA1 = ns[(size_t)nA * 64 + 32 + lane];
        float aB0 = ns[(size_t)nB * 64 + lane], aB1 = ns[(size_t)nB * 64 + 32 + lane];
        float tA = b1v, tB = b1v;
#pragma unroll
        for (int r = 0; r < 64; r++) {
            float w = sW1[r * 32 + lane];
            float vA = __shfl_sync(0xffffffffu, (r < 32) ? aA0 : aA1, r & 31);
            float vB = __shfl_sync(0xffffffffu, (r < 32) ? aB0 : aB1, r & 31);
            tA = fmaf(vA, w, tA);
            tB = fmaf(vB, w, tB);
        }
        tA = __fdividef(tA, 1.0f + __expf(-tA)) * (1.0f / 0.6f);
        tB = __fdividef(tB, 1.0f + __expf(-tB)) * (1.0f / 0.6f);
        u64 oA[3], oB[3];
#pragma unroll
        for (int k = 0; k < 3; k++) { oA[k] = bb[k]; oB[k] = bb[k]; }
#pragma unroll
        for (int r = 0; r < 32; r++) {
            u64 w0 = sW2u[r * 96 + lane];
            u64 w1 = sW2u[r * 96 + 32 + lane];
            u64 w2 = sW2u[r * 96 + 64 + lane];
            float vA = __shfl_sync(0xffffffffu, tA, r);
            float vB = __shfl_sync(0xffffffffu, tB, r);
            u64 vvA = pk2(vA, vA), vvB = pk2(vB, vB);
            oA[0] = ffma2(vvA, w0, oA[0]);
            oA[1] = ffma2(vvA, w1, oA[1]);
            oA[2] = ffma2(vvA, w2, oA[2]);
            oB[0] = ffma2(vvB, w0, oB[0]);
            oB[1] = ffma2(vvB, w1, oB[1]);
            oB[2] = ffma2(vvB, w2, oB[2]);
        }
        u64* outA = (u64*)g_sproj + (size_t)nA * 96;
#pragma unroll
        for (int k = 0; k < 3; k++) outA[lane + 32 * k] = oA[k];
        if (nB != nA) {
            u64* outB = (u64*)g_sproj + (size_t)nB * 96;
#pragma unroll
            for (int k = 0; k < 3; k++) outB[lane + 32 * k] = oB[k];
        }
    }
}

// ================= spherical-harmonic invariants (streamed) =================
__device__ __forceinline__ void sh_invariants(
    float xe, float ye, float ze, float xr, float yr, float zr, float* inv) {
    float nne = rsqrtf(xe * xe + ye * ye + ze * ze + 1e-12f);
    xe *= nne; ye *= nne; ze *= nne;
    float nnr = rsqrtf(xr * xr + yr * yr + zr * zr + 1e-12f);
    xr *= nnr; yr *= nnr; zr *= nnr;
    float st2e = xe * xe + ye * ye;
    float st2r = xr * xr + yr * yr;
    float ste = sqrtf(st2e), str = sqrtf(st2r);
    float c1e = (st2e > 0.0f) ? xe / ste : 0.0f;
    float s1e = (st2e > 0.0f) ? ye / ste : 0.0f;
    float c1r = (st2r > 0.0f) ? xr / str : 0.0f;
    float s1r = (st2r > 0.0f) ? yr / str : 0.0f;

    float acc[7];
#pragma unroll
    for (int l = 0; l < 7; l++) acc[l] = 0.0f;

    float de = 0.28209479177387814f, dr = 0.28209479177387814f;
    float ce = 1.0f, se = 0.0f, cr = 1.0f, sr = 0.0f;
#pragma unroll
    for (int m = 0; m <= 6; m++) {
        if (m > 0) {
            float km = sqrtf((2.0f * m + 1.0f) / (2.0f * m));
            de = -km * ste * de;
            dr = -km * str * dr;
            float ce2 = c1e * ce - s1e * se; se = s1e * ce + c1e * se; ce = ce2;
            float cr2 = c1r * cr - s1r * sr; sr = s1r * cr + c1r * sr; cr = cr2;
        }
        float w = (m == 0) ? 1.0f : 2.0f * (ce * cr + se * sr);
        float pe1 = de, pr1 = dr;
        acc[m] += w * pe1 * pr1;
        if (m < 6) {
            float kp = sqrtf(2.0f * m + 3.0f);
            float pe = kp * ze * de;
            float pr = kp * zr * dr;
            acc[m + 1] += w * pe * pr;
            float pe0 = pe1, pr0 = pr1;
#pragma unroll
            for (int l = m + 2; l <= 6; l++) {
                float fl = (float)l;
                float a = sqrtf((4.0f * fl * fl - 1.0f) / (fl * fl - (float)(m * m)));
                float b = sqrtf(((fl - 1.0f) * (fl - 1.0f) - (float)(m * m)) /
                                (4.0f * (fl - 1.0f) * (fl - 1.0f) - 1.0f));
                float pen = a * (ze * pe - b * pe0); pe0 = pe; pe = pen;
                float prn = a * (zr * pr - b * pr0); pr0 = pr; pr = prn;
                acc[l] += w * pe * pr;
            }
        }
    }
    const float fourpi = 12.566370614359172f;
#pragma unroll
    for (int l = 0; l < 7; l++) inv[l] = acc[l] * (fourpi / (2.0f * l + 1.0f));
}

// ================= kernel 5: per-edge geometric features =================
__global__ void k_geom(const float* __restrict__ ud, const int* __restrict__ eidx,
                       const float* __restrict__ ln_g, const float* __restrict__ ln_b,
                       int E) {
    int e = blockIdx.x * blockDim.x + threadIdx.x;
    if (e >= E) return;
    float ux = ud[e * 3 + 0], uy = ud[e * 3 + 1], uz = ud[e * 3 + 2];
    int i = __ldg(&eidx[E + e]);
    float rx = __ldg(&g_ref_vec[i * 3 + 0]);
    float ry = __ldg(&g_ref_vec[i * 3 + 1]);
    float rz = __ldg(&g_ref_vec[i * 3 + 2]);
    float inv[7];
    sh_invariants(ux, uy, uz, rx, ry, rz, inv);
    float mu = 0.0f;
#pragma unroll
    for (int l = 0; l < 7; l++) mu += inv[l];
    mu *= (1.0f / 7.0f);
    float var = 0.0f;
#pragma unroll
    for (int l = 0; l < 7; l++) { float d = inv[l] - mu; var += d * d; }
    var *= (1.0f / 7.0f);
    float isd = rsqrtf(var + 1e-5f);
    float o[8];
    o[0] = ux * rx + uy * ry + uz * rz;
#pragma unroll
    for (int l = 0; l < 7; l++)
        o[1 + l] = (inv[l] - mu) * isd * ln_g[l] + ln_b[l];
    float4* gg = (float4*)(g_geom + (size_t)e * 8);
    gg[0] = make_float4(o[0], o[1], o[2], o[3]);
    gg[1] = make_float4(o[4], o[5], o[6], o[7]);
}

// ================= kernel 6: tf32 MMA GEMM + fused gate epilogue =================
// Persistent CTAs, 256 threads = 8 warps (4 m-warps x 2 n-warps).
// Tile: 64 edges x 192 cols, K = 64. Warp: 16 edges x 96 cols (12 mma n-blocks).
// Processes edge range [e_begin, e_begin + e_count).
__global__ void __launch_bounds__(256, 2)
k_gemm(const float* __restrict__ rbf, const int* __restrict__ eidx,
       const float* __restrict__ W_edge, const float* __restrict__ b_edge,
       const float* __restrict__ W_inv, const float* __restrict__ b_inv,
       int e_begin, int e_count, int E) {
    extern __shared__ float sm[];
    float* sB  = sm;               // 192*68 (tf32 bits, n-major, padded)
    float* sA  = sB + 192 * 68;    // 64*68  (tf32 bits, row-major, padded)
    float* sG  = sA + 64 * 68;     // 64*8 geom
    float* sWi = sG + 512;         // 8*192 W_inv
    float* sBe = sWi + 1536;       // 192
    float* sBi = sBe + 192;        // 192
    int*   sJ  = (int*)(sBi + 192);  // 64

    int tid = threadIdx.x;
    int lane = tid & 31, warp = tid >> 5;
    int wm = warp >> 1, wn = warp & 1;
    int gid = lane >> 2, tig = lane & 3;

    // persistent staging: B=W_edge (tf32), W_inv, biases
    for (int i = tid; i < 64 * 192; i += 256) {
        int k = i / 192, n = i - k * 192;
        ((uint32_t*)sB)[n * 68 + k] = f2tf32(W_edge[i]);
    }
    for (int i = tid; i < 8 * 192; i += 256) sWi[i] = W_inv[i];
    if (tid < 192) { sBe[tid] = b_edge[tid]; sBi[tid] = b_inv[tid]; }

    const u64* sWi64 = (const u64*)sWi;
    const float2* sBe2 = (const float2*)sBe;
    const float2* sBi2 = (const float2*)sBi;
    const uint32_t* uA = (const uint32_t*)sA;
    const uint32_t* uB = (const uint32_t*)sB;

    int r0 = wm * 16 + gid;
    int nb_base = wn * 96;
    int e_end = e_begin + e_count;
    const float inv_sqrt3 = 0.57735026918962576f;

    int ntiles = (e_count + GTE - 1) / GTE;
    for (int t = blockIdx.x; t < ntiles; t += gridDim.x) {
        int e0 = e_begin + t * GTE;
        __syncthreads();  // staging buffers free (also covers first-iter staging)

        // stage A tile (cvt to tf32)
        for (int i = tid; i < 64 * 16; i += 256) {
            int r = i >> 4, c4 = i & 15;
            int e = min(e0 + r, E - 1);
            float4 v = __ldg((const float4*)(rbf + (size_t)e * 64 + c4 * 4));
            uint4 u;
            u.x = f2tf32(v.x); u.y = f2tf32(v.y);
            u.z = f2tf32(v.z); u.w = f2tf32(v.w);
            *(uint4*)(sA + r * 68 + c4 * 4) = u;
        }
        // stage geom + j-index
        if (tid < 128) {
            int e = min(e0 + (tid >> 1), E - 1);
            ((float4*)sG)[tid] =
                __ldg((const float4*)(g_geom + (size_t)e * 8) + (tid & 1));
        }
        if (tid < 64) sJ[tid] = __ldg(&eidx[min(e0 + tid, E - 1)]);
        __syncthreads();

        // ---- MMA mainloop ----
        float acc[12][4];
#pragma unroll
        for (int nb = 0; nb < 12; nb++)
            acc[nb][0] = acc[nb][1] = acc[nb][2] = acc[nb][3] = 0.0f;
#pragma unroll
        for (int kc = 0; kc < 8; kc++) {
            int k0 = kc * 8 + tig;
            uint32_t a0 = uA[r0 * 68 + k0];
            uint32_t a1 = uA[(r0 + 8) * 68 + k0];
            uint32_t a2 = uA[r0 * 68 + k0 + 4];
            uint32_t a3 = uA[(r0 + 8) * 68 + k0 + 4];
#pragma unroll
            for (int nb = 0; nb < 12; nb++) {
                int n = nb_base + nb * 8 + gid;
                uint32_t b0 = uB[n * 68 + k0];
                uint32_t b1 = uB[n * 68 + k0 + 4];
                mma_tf32(acc[nb], a0, a1, a2, a3, b0, b1);
            }
        }

        // ---- fused epilogue: gate + bias + sproj, per (edge,col) element ----
        u64 gr0[8], gr1[8];
#pragma unroll
        for (int q = 0; q < 8; q++) {
            float v0 = sG[r0 * 8 + q], v1 = sG[(r0 + 8) * 8 + q];
            gr0[q] = pk2(v0, v0);
            gr1[q] = pk2(v1, v1);
        }
        int j0 = sJ[r0], j1 = sJ[r0 + 8];
        bool val0 = (e0 + r0) < e_end, val1 = (e0 + r0 + 8) < e_end;
        float* xrow0 = g_x + (size_t)(e0 + r0) * 192;
        float* xrow1 = g_x + (size_t)(e0 + r0 + 8) * 192;
#pragma unroll
        for (int nb = 0; nb < 12; nb++) {
            int col = nb_base + nb * 8 + tig * 2;
            int ch = col >> 1;
            u64 g0 = 0ull, g1 = 0ull;
#pragma unroll
            for (int q = 0; q < 8; q++) {
                u64 w = sWi64[q * 96 + ch];
                g0 = ffma2(gr0[q], w, g0);
                g1 = ffma2(gr1[q], w, g1);
            }
            float2 bi = sBi2[ch];
            float2 be = sBe2[ch];
            float g00, g01, g10, g11;
            upk2(g0, g00, g01);
            upk2(g1, g10, g11);
            float f00 = gatef(g00 + bi.x), f01 = gatef(g01 + bi.y);
            float f10 = gatef(g10 + bi.x), f11 = gatef(g11 + bi.y);
            float2 sp0 = __ldg((const float2*)(g_sproj + (size_t)j0 * 192 + col));
            float2 sp1 = __ldg((const float2*)(g_sproj + (size_t)j1 * 192 + col));
            float x00 = sp0.x * (acc[nb][0] + be.x) * f00 * inv_sqrt3;
            float x01 = sp0.y * (acc[nb][1] + be.y) * f01 * inv_sqrt3;
            float x10 = sp1.x * (acc[nb][2] + be.x) * f10 * inv_sqrt3;
            float x11 = sp1.y * (acc[nb][3] + be.y) * f11 * inv_sqrt3;
            if (val0) *(float2*)(xrow0 + col) = make_float2(x00, x01);
            if (val1) *(float2*)(xrow1 + col) = make_float2(x10, x11);
        }
    }
}

// ================= kernel 7: scatter (warp per edge), edge range =================
__global__ void __launch_bounds__(256)
k_scatter(const float* __restrict__ ud, const int* __restrict__ eidx,
          const float* __restrict__ nv, float* __restrict__ out,
          int N, int E, int e_begin, int e_count) {
    __shared__ __align__(16) float sX[8][192];
    int lane = threadIdx.x & 31, warp = threadIdx.x >> 5;
    float* xf = sX[warp];
    float* outv = out + (size_t)N * 64;
    const float ish = 0.125f;
    int e_end = e_begin + e_count;

    for (int e = e_begin + blockIdx.x * 8 + warp; e < e_end; e += gridDim.x * 8) {
        const float2* xr = (const float2*)(g_x + (size_t)e * 192);
        float2 v0 = __ldg(xr + lane);        // x1: h = 2lane, 2lane+1
        float2 v1 = __ldg(xr + 32 + lane);   // x2
        float2 v2 = __ldg(xr + 64 + lane);   // x3
        ((float2*)xf)[lane] = v0;
        ((float2*)xf)[32 + lane] = v1;
        ((float2*)xf)[64 + lane] = v2;
        int j = __ldg(&eidx[e]), in = __ldg(&eidx[E + e]);
        float ud0 = __ldg(&ud[e * 3 + 0]);
        float ud1 = __ldg(&ud[e * 3 + 1]);
        float ud2 = __ldg(&ud[e * 3 + 2]);
        __syncwarp();

        if (lane < 16) {  // delta_scalar: x3
            const float4 x3v = *(const float4*)&xf[128 + 4 * lane];
            red4(&out[(size_t)in * 64 + 4 * lane], x3v.x, x3v.y, x3v.z, x3v.w);
        }
        {  // delta_vector d=0,1: o = 4*lane in [0,128)
            int o = 4 * lane;
            float udd = (o >> 6) ? ud1 : ud0;
            int h = o & 63;
            const float4 f1 = *(const float4*)&xf[h];
            const float4 f2 = *(const float4*)&xf[64 + h];
            float4 nvv = __ldg((const float4*)(nv + (size_t)j * 192 + o));
            red4(&outv[(size_t)in * 192 + o],
                 (f1.x * nvv.x + f2.x * udd) * ish,
                 (f1.y * nvv.y + f2.y * udd) * ish,
                 (f1.z * nvv.z + f2.z * udd) * ish,
                 (f1.w * nvv.w + f2.w * udd) * ish);
        }
        if (lane < 16) {  // delta_vector d=2
            int o = 128 + 4 * lane;
            int h = 4 * lane;
            const float4 f1 = *(const float4*)&xf[h];
            const float4 f2 = *(const float4*)&xf[64 + h];
            float4 nvv = __ldg((const float4*)(nv + (size_t)j * 192 + o));
            red4(&outv[(size_t)in * 192 + o],
                 (f1.x * nvv.x + f2.x * ud2) * ish,
                 (f1.y * nvv.y + f2.y * ud2) * ish,
                 (f1.z * nvv.z + f2.z * ud2) * ish,
                 (f1.w * nvv.w + f2.w * ud2) * ish);
        }
        __syncwarp();
    }
}

// ================= launch =================
extern "C" void kernel_launch(void* const* d_in, const int* in_sizes, int n_in,
                              void* d_out, int out_size) {
    const float* node_scalar = (const float*)d_in[0];
    const float* node_vector = (const float*)d_in[1];
    const float* edge_rbf    = (const float*)d_in[2];
    const float* edge_udiff  = (const float*)d_in[3];
    const int*   edge_index  = (const int*)d_in[4];
    const float* W_edge      = (const float*)d_in[5];
    const float* b_edge      = (const float*)d_in[6];
    const float* W_x1        = (const float*)d_in[7];
    const float* b_x1        = (const float*)d_in[8];
    const float* W_x2        = (const float*)d_in[9];
    const float* b_x2        = (const float*)d_in[10];
    const float* ln_g        = (const float*)d_in[11];
    const float* ln_b        = (const float*)d_in[12];
    const float* W_inv       = (const float*)d_in[13];
    const float* b_inv       = (const float*)d_in[14];

    int N = in_sizes[0] / 64;
    int E = in_sizes[3] / 3;
    float* out = (float*)d_out;

    // dynamic smem for k_gemm: B + A + geom + W_inv + biases + J
    int smem_gemm = (192 * 68 + 64 * 68 + 512 + 1536 + 192 + 192) * 4 + 64 * 4;
    cudaFuncSetAttribute(k_gemm, cudaFuncAttributeMaxDynamicSharedMemorySize,
                         smem_gemm);

    k_zero<<<1024, 256>>>((float4*)out, out_size / 4, N);
    k_refaccum<<<(E + 255) / 256, 256>>>(edge_udiff, edge_index, E);
    k_refvec<<<(N + 255) / 256, 256>>>(N);
    k_sproj<<<888, 256>>>(node_scalar, W_x1, b_x1, W_x2, b_x2, N);
    k_geom<<<(E + 255) / 256, 256>>>(edge_udiff, edge_index, ln_g, ln_b, E);

    // chunked gemm -> scatter so g_x stays L2-resident between producer/consumer
    for (int c0 = 0; c0 < E; c0 += CHUNK) {
        int cnt = min(CHUNK, E - c0);
        k_gemm<<<296, 256, smem_gemm>>>(edge_rbf, edge_index, W_edge, b_edge,
                                        W_inv, b_inv, c0, cnt, E);
        int sgrid = min(2960, (cnt + 7) / 8);
        k_scatter<<<sgrid, 256>>>(edge_udiff, edge_index, node_vector, out,
                                  N, E, c0, cnt);
    }
}

// round 9
// speedup vs baseline: 1.2225x; 1.2225x over previous
#include <cuda_runtime.h>
#include <math.h>
#include <stdint.h>

#define NMAX 50000
#define EMAX 400000
#define GTE 64   // edges per gemm tile

// ---- scratch (device globals; no allocation allowed) ----
__device__ float g_ref_accum[NMAX * 4];   // sum x,y,z + count
__device__ float g_ref_vec[NMAX * 3];
__device__ float g_sproj[(size_t)NMAX * 192];
__device__ float g_geom[(size_t)EMAX * 8];
__device__ float g_x[(size_t)EMAX * 192];  // gated per-edge messages

// ---------------- helpers ----------------
typedef unsigned long long u64;
__device__ __forceinline__ u64 pk2(float lo, float hi) {
    u64 r;
    asm("mov.b64 %0, {%1, %2};" : "=l"(r) : "f"(lo), "f"(hi));
    return r;
}
__device__ __forceinline__ void upk2(u64 v, float& lo, float& hi) {
    asm("mov.b64 {%0, %1}, %2;" : "=f"(lo), "=f"(hi) : "l"(v));
}
__device__ __forceinline__ u64 ffma2(u64 a, u64 b, u64 c) {
    u64 d;
    asm("fma.rn.f32x2 %0, %1, %2, %3;" : "=l"(d) : "l"(a), "l"(b), "l"(c));
    return d;
}
__device__ __forceinline__ float tanh_fast(float x) {
    float y;
    asm("tanh.approx.f32 %0, %1;" : "=f"(y) : "f"(x));
    return y;
}
__device__ __forceinline__ void red4(float* a, float x, float y, float z, float w) {
    asm volatile("red.global.add.v4.f32 [%0], {%1, %2, %3, %4};"
                 :: "l"(a), "f"(x), "f"(y), "f"(z), "f"(w) : "memory");
}
__device__ __forceinline__ uint32_t f2tf32(float v) {
    uint32_t t;
    asm("cvt.rna.tf32.f32 %0, %1;" : "=r"(t) : "f"(v));
    return t;
}
__device__ __forceinline__ void mma_tf32(float c[4], uint32_t a0, uint32_t a1,
                                         uint32_t a2, uint32_t a3,
                                         uint32_t b0, uint32_t b1) {
    asm volatile(
        "mma.sync.aligned.m16n8k8.row.col.f32.tf32.tf32.f32 "
        "{%0,%1,%2,%3}, {%4,%5,%6,%7}, {%8,%9}, {%0,%1,%2,%3};"
        : "+f"(c[0]), "+f"(c[1]), "+f"(c[2]), "+f"(c[3])
        : "r"(a0), "r"(a1), "r"(a2), "r"(a3), "r"(b0), "r"(b1));
}
__device__ __forceinline__ float gatef(float g) {
    float sg = __fdividef(g, 1.0f + __expf(-g)) * (1.0f / 0.6f);
    return 1.0f + tanh_fast(sg);
}

// ================= kernel 1: zero output + accumulators =================
__global__ void k_zero(float4* __restrict__ out4, int n_out4, int n_acc4) {
    float4* acc4 = (float4*)g_ref_accum;
    int total = n_out4 + n_acc4;
    float4 z = make_float4(0.f, 0.f, 0.f, 0.f);
    for (int i = blockIdx.x * blockDim.x + threadIdx.x; i < total;
         i += gridDim.x * blockDim.x) {
        if (i < n_out4) out4[i] = z;
        else acc4[i - n_out4] = z;
    }
}

// ================= kernel 2: segment-sum of edge_udiff over i =================
__global__ void k_refaccum(const float* __restrict__ ud,
                           const int* __restrict__ eidx, int E) {
    int e = blockIdx.x * blockDim.x + threadIdx.x;
    if (e >= E) return;
    int i = eidx[E + e];
    red4(&g_ref_accum[i * 4], ud[e * 3 + 0], ud[e * 3 + 1], ud[e * 3 + 2], 1.0f);
}

// ================= kernel 3: normalize ref vector per node =================
__global__ void k_refvec(int N) {
    int n = blockIdx.x * blockDim.x + threadIdx.x;
    if (n >= N) return;
    float4 a = *(const float4*)&g_ref_accum[n * 4];
    float ic = 1.0f / fmaxf(a.w, 1.0f);
    float rx = a.x * ic, ry = a.y * ic, rz = a.z * ic;
    float norm = sqrtf(rx * rx + ry * ry + rz * rz + 1e-9f);
    float inm = 1.0f / norm;
    rx *= inm; ry *= inm; rz *= inm;
    if (norm < 5e-5f) { rx = 1.0f; ry = 0.0f; rz = 0.0f; }
    g_ref_vec[n * 3 + 0] = rx;
    g_ref_vec[n * 3 + 1] = ry;
    g_ref_vec[n * 3 + 2] = rz;
}

// ================= kernel 4: node scalar MLP projection =================
__global__ void __launch_bounds__(256)
k_sproj(const float* __restrict__ ns, const float* __restrict__ W1,
        const float* __restrict__ b1, const float* __restrict__ W2,
        const float* __restrict__ b2, int N) {
    __shared__ float sW1[64 * 32];
    __shared__ float sW2[32 * 192];
    int tid = threadIdx.x;
    for (int q = tid; q < 64 * 32; q += 256) sW1[q] = W1[q];
    for (int q = tid; q < 32 * 192; q += 256) sW2[q] = W2[q];
    __syncthreads();
    const u64* sW2u = (const u64*)sW2;
    const float2* b2p = (const float2*)b2;
    int lane = tid & 31, warp = tid >> 5;

    u64 bb[3];
#pragma unroll
    for (int k = 0; k < 3; k++) {
        float2 t = b2p[lane + 32 * k];
        bb[k] = pk2(t.x, t.y);
    }
    float b1v = b1[lane];

    int npairs = (N + 1) >> 1;
    for (int p = blockIdx.x * 8 + warp; p < npairs; p += gridDim.x * 8) {
        int nA = p * 2;
        int nB = min(nA + 1, N - 1);
        float aA0 = ns[(size_t)nA * 64 + lane], aA1 = ns[(size_t)nA * 64 + 32 + lane];
        float aB0 = ns[(size_t)nB * 64 + lane], aB1 = ns[(size_t)nB * 64 + 32 + lane];
        float tA = b1v, tB = b1v;
#pragma unroll
        for (int r = 0; r < 64; r++) {
            float w = sW1[r * 32 + lane];
            float vA = __shfl_sync(0xffffffffu, (r < 32) ? aA0 : aA1, r & 31);
            float vB = __shfl_sync(0xffffffffu, (r < 32) ? aB0 : aB1, r & 31);
            tA = fmaf(vA, w, tA);
            tB = fmaf(vB, w, tB);
        }
        tA = __fdividef(tA, 1.0f + __expf(-tA)) * (1.0f / 0.6f);
        tB = __fdividef(tB, 1.0f + __expf(-tB)) * (1.0f / 0.6f);
        u64 oA[3], oB[3];
#pragma unroll
        for (int k = 0; k < 3; k++) { oA[k] = bb[k]; oB[k] = bb[k]; }
#pragma unroll
        for (int r = 0; r < 32; r++) {
            u64 w0 = sW2u[r * 96 + lane];
            u64 w1 = sW2u[r * 96 + 32 + lane];
            u64 w2 = sW2u[r * 96 + 64 + lane];
            float vA = __shfl_sync(0xffffffffu, tA, r);
            float vB = __shfl_sync(0xffffffffu, tB, r);
            u64 vvA = pk2(vA, vA), vvB = pk2(vB, vB);
            oA[0] = ffma2(vvA, w0, oA[0]);
            oA[1] = ffma2(vvA, w1, oA[1]);
            oA[2] = ffma2(vvA, w2, oA[2]);
            oB[0] = ffma2(vvB, w0, oB[0]);
            oB[1] = ffma2(vvB, w1, oB[1]);
            oB[2] = ffma2(vvB, w2, oB[2]);
        }
        u64* outA = (u64*)g_sproj + (size_t)nA * 96;
#pragma unroll
        for (int k = 0; k < 3; k++) outA[lane + 32 * k] = oA[k];
        if (nB != nA) {
            u64* outB = (u64*)g_sproj + (size_t)nB * 96;
#pragma unroll
            for (int k = 0; k < 3; k++) outB[lane + 32 * k] = oB[k];
        }
    }
}

// ================= spherical-harmonic invariants (streamed) =================
__device__ __forceinline__ void sh_invariants(
    float xe, float ye, float ze, float xr, float yr, float zr, float* inv) {
    float nne = rsqrtf(xe * xe + ye * ye + ze * ze + 1e-12f);
    xe *= nne; ye *= nne; ze *= nne;
    float nnr = rsqrtf(xr * xr + yr * yr + zr * zr + 1e-12f);
    xr *= nnr; yr *= nnr; zr *= nnr;
    float st2e = xe * xe + ye * ye;
    float st2r = xr * xr + yr * yr;
    float ste = sqrtf(st2e), str = sqrtf(st2r);
    float c1e = (st2e > 0.0f) ? xe / ste : 0.0f;
    float s1e = (st2e > 0.0f) ? ye / ste : 0.0f;
    float c1r = (st2r > 0.0f) ? xr / str : 0.0f;
    float s1r = (st2r > 0.0f) ? yr / str : 0.0f;

    float acc[7];
#pragma unroll
    for (int l = 0; l < 7; l++) acc[l] = 0.0f;

    float de = 0.28209479177387814f, dr = 0.28209479177387814f;
    float ce = 1.0f, se = 0.0f, cr = 1.0f, sr = 0.0f;
#pragma unroll
    for (int m = 0; m <= 6; m++) {
        if (m > 0) {
            float km = sqrtf((2.0f * m + 1.0f) / (2.0f * m));
            de = -km * ste * de;
            dr = -km * str * dr;
            float ce2 = c1e * ce - s1e * se; se = s1e * ce + c1e * se; ce = ce2;
            float cr2 = c1r * cr - s1r * sr; sr = s1r * cr + c1r * sr; cr = cr2;
        }
        float w = (m == 0) ? 1.0f : 2.0f * (ce * cr + se * sr);
        float pe1 = de, pr1 = dr;
        acc[m] += w * pe1 * pr1;
        if (m < 6) {
            float kp = sqrtf(2.0f * m + 3.0f);
            float pe = kp * ze * de;
            float pr = kp * zr * dr;
            acc[m + 1] += w * pe * pr;
            float pe0 = pe1, pr0 = pr1;
#pragma unroll
            for (int l = m + 2; l <= 6; l++) {
                float fl = (float)l;
                float a = sqrtf((4.0f * fl * fl - 1.0f) / (fl * fl - (float)(m * m)));
                float b = sqrtf(((fl - 1.0f) * (fl - 1.0f) - (float)(m * m)) /
                                (4.0f * (fl - 1.0f) * (fl - 1.0f) - 1.0f));
                float pen = a * (ze * pe - b * pe0); pe0 = pe; pe = pen;
                float prn = a * (zr * pr - b * pr0); pr0 = pr; pr = prn;
                acc[l] += w * pe * pr;
            }
        }
    }
    const float fourpi = 12.566370614359172f;
#pragma unroll
    for (int l = 0; l < 7; l++) inv[l] = acc[l] * (fourpi / (2.0f * l + 1.0f));
}

// ================= kernel 5: per-edge geometric features =================
__global__ void k_geom(const float* __restrict__ ud, const int* __restrict__ eidx,
                       const float* __restrict__ ln_g, const float* __restrict__ ln_b,
                       int E) {
    int e = blockIdx.x * blockDim.x + threadIdx.x;
    if (e >= E) return;
    float ux = ud[e * 3 + 0], uy = ud[e * 3 + 1], uz = ud[e * 3 + 2];
    int i = __ldg(&eidx[E + e]);
    float rx = __ldg(&g_ref_vec[i * 3 + 0]);
    float ry = __ldg(&g_ref_vec[i * 3 + 1]);
    float rz = __ldg(&g_ref_vec[i * 3 + 2]);
    float inv[7];
    sh_invariants(ux, uy, uz, rx, ry, rz, inv);
    float mu = 0.0f;
#pragma unroll
    for (int l = 0; l < 7; l++) mu += inv[l];
    mu *= (1.0f / 7.0f);
    float var = 0.0f;
#pragma unroll
    for (int l = 0; l < 7; l++) { float d = inv[l] - mu; var += d * d; }
    var *= (1.0f / 7.0f);
    float isd = rsqrtf(var + 1e-5f);
    float o[8];
    o[0] = ux * rx + uy * ry + uz * rz;
#pragma unroll
    for (int l = 0; l < 7; l++)
        o[1 + l] = (inv[l] - mu) * isd * ln_g[l] + ln_b[l];
    float4* gg = (float4*)(g_geom + (size_t)e * 8);
    gg[0] = make_float4(o[0], o[1], o[2], o[3]);
    gg[1] = make_float4(o[4], o[5], o[6], o[7]);
}

// ================= kernel 6: tf32 MMA GEMM + fused gate epilogue =================
// Persistent CTAs, 256 threads = 8 warps (4 m-warps x 2 n-warps).
// Tile: 64 edges x 192 cols, K = 64. Warp: 16 edges x 96 cols (12 mma n-blocks).
// x results staged through smem and written to g_x fully coalesced.
#define XS_STR 100   // staging row stride (floats)

__global__ void __launch_bounds__(256, 2)
k_gemm(const float* __restrict__ rbf, const int* __restrict__ eidx,
       const float* __restrict__ W_edge, const float* __restrict__ b_edge,
       const float* __restrict__ W_inv, const float* __restrict__ b_inv,
       int E) {
    extern __shared__ float sm[];
    float* sB  = sm;                  // 192*68 (tf32 bits, n-major, padded)
    float* sA  = sB + 192 * 68;       // 64*68  (tf32 bits, row-major, padded)
    float* sXs = sA + 64 * 68;        // 64*XS_STR staging (25.6KB)
    float* sG  = sXs + 64 * XS_STR;   // 64*8 geom
    float* sWi = sG + 512;            // 8*192 W_inv
    float* sBe = sWi + 1536;          // 192
    float* sBi = sBe + 192;           // 192
    int*   sJ  = (int*)(sBi + 192);   // 64

    int tid = threadIdx.x;
    int lane = tid & 31, warp = tid >> 5;
    int wm = warp >> 1, wn = warp & 1;
    int gid = lane >> 2, tig = lane & 3;

    // persistent staging: B=W_edge (tf32), W_inv, biases
    for (int i = tid; i < 64 * 192; i += 256) {
        int k = i / 192, n = i - k * 192;
        ((uint32_t*)sB)[n * 68 + k] = f2tf32(W_edge[i]);
    }
    for (int i = tid; i < 8 * 192; i += 256) sWi[i] = W_inv[i];
    if (tid < 192) { sBe[tid] = b_edge[tid]; sBi[tid] = b_inv[tid]; }

    const u64* sWi64 = (const u64*)sWi;
    const float2* sBe2 = (const float2*)sBe;
    const float2* sBi2 = (const float2*)sBi;
    const uint32_t* uA = (const uint32_t*)sA;
    const uint32_t* uB = (const uint32_t*)sB;

    int r0 = wm * 16 + gid;
    int nb_base = wn * 96;
    const float inv_sqrt3 = 0.57735026918962576f;

    int ntiles = (E + GTE - 1) / GTE;
    for (int t = blockIdx.x; t < ntiles; t += gridDim.x) {
        int e0 = t * GTE;
        __syncthreads();  // staging buffers free (also covers first-iter staging)

        // stage A tile (cvt to tf32)
        for (int i = tid; i < 64 * 16; i += 256) {
            int r = i >> 4, c4 = i & 15;
            int e = min(e0 + r, E - 1);
            float4 v = __ldg((const float4*)(rbf + (size_t)e * 64 + c4 * 4));
            uint4 u;
            u.x = f2tf32(v.x); u.y = f2tf32(v.y);
            u.z = f2tf32(v.z); u.w = f2tf32(v.w);
            *(uint4*)(sA + r * 68 + c4 * 4) = u;
        }
        // stage geom + j-index
        if (tid < 128) {
            int e = min(e0 + (tid >> 1), E - 1);
            ((float4*)sG)[tid] =
                __ldg((const float4*)(g_geom + (size_t)e * 8) + (tid & 1));
        }
        if (tid < 64) sJ[tid] = __ldg(&eidx[min(e0 + tid, E - 1)]);
        __syncthreads();

        // ---- MMA mainloop ----
        float acc[12][4];
#pragma unroll
        for (int nb = 0; nb < 12; nb++)
            acc[nb][0] = acc[nb][1] = acc[nb][2] = acc[nb][3] = 0.0f;
#pragma unroll
        for (int kc = 0; kc < 8; kc++) {
            int k0 = kc * 8 + tig;
            uint32_t a0 = uA[r0 * 68 + k0];
            uint32_t a1 = uA[(r0 + 8) * 68 + k0];
            uint32_t a2 = uA[r0 * 68 + k0 + 4];
            uint32_t a3 = uA[(r0 + 8) * 68 + k0 + 4];
#pragma unroll
            for (int nb = 0; nb < 12; nb++) {
                int n = nb_base + nb * 8 + gid;
                uint32_t b0 = uB[n * 68 + k0];
                uint32_t b1 = uB[n * 68 + k0 + 4];
                mma_tf32(acc[nb], a0, a1, a2, a3, b0, b1);
            }
        }

        // ---- fused epilogue: gate + bias + sproj; results back into acc ----
        u64 gr0[8], gr1[8];
#pragma unroll
        for (int q = 0; q < 8; q++) {
            float v0 = sG[r0 * 8 + q], v1 = sG[(r0 + 8) * 8 + q];
            gr0[q] = pk2(v0, v0);
            gr1[q] = pk2(v1, v1);
        }
        int j0 = sJ[r0], j1 = sJ[r0 + 8];
#pragma unroll
        for (int nb = 0; nb < 12; nb++) {
            int col = nb_base + nb * 8 + tig * 2;
            int ch = col >> 1;
            u64 g0 = 0ull, g1 = 0ull;
#pragma unroll
            for (int q = 0; q < 8; q++) {
                u64 w = sWi64[q * 96 + ch];
                g0 = ffma2(gr0[q], w, g0);
                g1 = ffma2(gr1[q], w, g1);
            }
            float2 bi = sBi2[ch];
            float2 be = sBe2[ch];
            float g00, g01, g10, g11;
            upk2(g0, g00, g01);
            upk2(g1, g10, g11);
            float f00 = gatef(g00 + bi.x), f01 = gatef(g01 + bi.y);
            float f10 = gatef(g10 + bi.x), f11 = gatef(g11 + bi.y);
            float2 sp0 = __ldg((const float2*)(g_sproj + (size_t)j0 * 192 + col));
            float2 sp1 = __ldg((const float2*)(g_sproj + (size_t)j1 * 192 + col));
            acc[nb][0] = sp0.x * (acc[nb][0] + be.x) * f00 * inv_sqrt3;
            acc[nb][1] = sp0.y * (acc[nb][1] + be.y) * f01 * inv_sqrt3;
            acc[nb][2] = sp1.x * (acc[nb][2] + be.x) * f10 * inv_sqrt3;
            acc[nb][3] = sp1.y * (acc[nb][3] + be.y) * f11 * inv_sqrt3;
        }

        // ---- two-pass staged, fully coalesced g_x writes ----
#pragma unroll
        for (int pass = 0; pass < 2; pass++) {
            if (wn == pass) {
#pragma unroll
                for (int nb = 0; nb < 12; nb++) {
                    int cl = nb * 8 + tig * 2;  // local col within the 96-block
                    *(float2*)(sXs + r0 * XS_STR + cl) =
                        make_float2(acc[nb][0], acc[nb][1]);
                    *(float2*)(sXs + (r0 + 8) * XS_STR + cl) =
                        make_float2(acc[nb][2], acc[nb][3]);
                }
            }
            __syncthreads();
            // 64 rows x 96 cols = 1536 float4; 6 per thread, coalesced
            for (int i = tid; i < 1536; i += 256) {
                int r = i / 24, c4 = i % 24;
                if (e0 + r < E)
                    *(float4*)(g_x + (size_t)(e0 + r) * 192 + pass * 96 + c4 * 4) =
                        *(const float4*)(sXs + r * XS_STR + c4 * 4);
            }
            __syncthreads();
        }
    }
}

// ================= kernel 7: scatter (warp per edge) =================
__global__ void __launch_bounds__(256)
k_scatter(const float* __restrict__ ud, const int* __restrict__ eidx,
          const float* __restrict__ nv, float* __restrict__ out, int N, int E) {
    __shared__ __align__(16) float sX[8][192];
    int lane = threadIdx.x & 31, warp = threadIdx.x >> 5;
    float* xf = sX[warp];
    float* outv = out + (size_t)N * 64;
    const float ish = 0.125f;

    for (int e = blockIdx.x * 8 + warp; e < E; e += gridDim.x * 8) {
        const float2* xr = (const float2*)(g_x + (size_t)e * 192);
        float2 v0 = __ldg(xr + lane);        // x1: h = 2lane, 2lane+1
        float2 v1 = __ldg(xr + 32 + lane);   // x2
        float2 v2 = __ldg(xr + 64 + lane);   // x3
        ((float2*)xf)[lane] = v0;
        ((float2*)xf)[32 + lane] = v1;
        ((float2*)xf)[64 + lane] = v2;
        int j = __ldg(&eidx[e]), in = __ldg(&eidx[E + e]);
        float ud0 = __ldg(&ud[e * 3 + 0]);
        float ud1 = __ldg(&ud[e * 3 + 1]);
        float ud2 = __ldg(&ud[e * 3 + 2]);
        __syncwarp();

        if (lane < 16) {  // delta_scalar: x3
            const float4 x3v = *(const float4*)&xf[128 + 4 * lane];
            red4(&out[(size_t)in * 64 + 4 * lane], x3v.x, x3v.y, x3v.z, x3v.w);
        }
        {  // delta_vector d=0,1: o = 4*lane in [0,128)
            int o = 4 * lane;
            float udd = (o >> 6) ? ud1 : ud0;
            int h = o & 63;
            const float4 f1 = *(const float4*)&xf[h];
            const float4 f2 = *(const float4*)&xf[64 + h];
            float4 nvv = __ldg((const float4*)(nv + (size_t)j * 192 + o));
            red4(&outv[(size_t)in * 192 + o],
                 (f1.x * nvv.x + f2.x * udd) * ish,
                 (f1.y * nvv.y + f2.y * udd) * ish,
                 (f1.z * nvv.z + f2.z * udd) * ish,
                 (f1.w * nvv.w + f2.w * udd) * ish);
        }
        if (lane < 16) {  // delta_vector d=2
            int o = 128 + 4 * lane;
            int h = 4 * lane;
            const float4 f1 = *(const float4*)&xf[h];
            const float4 f2 = *(const float4*)&xf[64 + h];
            float4 nvv = __ldg((const float4*)(nv + (size_t)j * 192 + o));
            red4(&outv[(size_t)in * 192 + o],
                 (f1.x * nvv.x + f2.x * ud2) * ish,
                 (f1.y * nvv.y + f2.y * ud2) * ish,
                 (f1.z * nvv.z + f2.z * ud2) * ish,
                 (f1.w * nvv.w + f2.w * ud2) * ish);
        }
        __syncwarp();
    }
}

// ================= launch =================
extern "C" void kernel_launch(void* const* d_in, const int* in_sizes, int n_in,
                              void* d_out, int out_size) {
    const float* node_scalar = (const float*)d_in[0];
    const float* node_vector = (const float*)d_in[1];
    const float* edge_rbf    = (const float*)d_in[2];
    const float* edge_udiff  = (const float*)d_in[3];
    const int*   edge_index  = (const int*)d_in[4];
    const float* W_edge      = (const float*)d_in[5];
    const float* b_edge      = (const float*)d_in[6];
    const float* W_x1        = (const float*)d_in[7];
    const float* b_x1        = (const float*)d_in[8];
    const float* W_x2        = (const float*)d_in[9];
    const float* b_x2        = (const float*)d_in[10];
    const float* ln_g        = (const float*)d_in[11];
    const float* ln_b        = (const float*)d_in[12];
    const float* W_inv       = (const float*)d_in[13];
    const float* b_inv       = (const float*)d_in[14];

    int N = in_sizes[0] / 64;
    int E = in_sizes[3] / 3;
    float* out = (float*)d_out;

    // dynamic smem for k_gemm: B + A + Xstage + geom + W_inv + biases + J
    int smem_gemm = (192 * 68 + 64 * 68 + 64 * XS_STR + 512 + 1536 + 192 + 192) * 4
                    + 64 * 4;
    cudaFuncSetAttribute(k_gemm, cudaFuncAttributeMaxDynamicSharedMemorySize,
                         smem_gemm);

    k_zero<<<1024, 256>>>((float4*)out, out_size / 4, N);
    k_refaccum<<<(E + 255) / 256, 256>>>(edge_udiff, edge_index, E);
    k_refvec<<<(N + 255) / 256, 256>>>(N);
    k_sproj<<<888, 256>>>(node_scalar, W_x1, b_x1, W_x2, b_x2, N);
    k_geom<<<(E + 255) / 256, 256>>>(edge_udiff, edge_index, ln_g, ln_b, E);
    k_gemm<<<296, 256, smem_gemm>>>(edge_rbf, edge_index, W_edge, b_edge,
                                    W_inv, b_inv, E);
    k_scatter<<<2960, 256>>>(edge_udiff, edge_index, node_vector, out, N, E);
}

// round 10
// speedup vs baseline: 1.4212x; 1.1626x over previous
#include <cuda_runtime.h>
#include <cuda_fp16.h>
#include <math.h>
#include <stdint.h>

#define NMAX 50000
#define EMAX 400000
#define GTE 64   // edges per gemm tile

// ---- scratch (device globals; no allocation allowed) ----
__device__ float g_ref_accum[NMAX * 4];   // sum x,y,z + count
__device__ float g_ref_vec[NMAX * 3];
__device__ float g_sproj[(size_t)NMAX * 192];
__device__ float g_geom[(size_t)EMAX * 8];
__device__ __half g_x[(size_t)EMAX * 192];  // gated per-edge messages (fp16)

// ---------------- helpers ----------------
typedef unsigned long long u64;
__device__ __forceinline__ u64 pk2(float lo, float hi) {
    u64 r;
    asm("mov.b64 %0, {%1, %2};" : "=l"(r) : "f"(lo), "f"(hi));
    return r;
}
__device__ __forceinline__ void upk2(u64 v, float& lo, float& hi) {
    asm("mov.b64 {%0, %1}, %2;" : "=f"(lo), "=f"(hi) : "l"(v));
}
__device__ __forceinline__ u64 ffma2(u64 a, u64 b, u64 c) {
    u64 d;
    asm("fma.rn.f32x2 %0, %1, %2, %3;" : "=l"(d) : "l"(a), "l"(b), "l"(c));
    return d;
}
__device__ __forceinline__ float tanh_fast(float x) {
    float y;
    asm("tanh.approx.f32 %0, %1;" : "=f"(y) : "f"(x));
    return y;
}
__device__ __forceinline__ void red4(float* a, float x, float y, float z, float w) {
    asm volatile("red.global.add.v4.f32 [%0], {%1, %2, %3, %4};"
                 :: "l"(a), "f"(x), "f"(y), "f"(z), "f"(w) : "memory");
}
__device__ __forceinline__ uint32_t f2tf32(float v) {
    uint32_t t;
    asm("cvt.rna.tf32.f32 %0, %1;" : "=r"(t) : "f"(v));
    return t;
}
__device__ __forceinline__ void mma_tf32(float c[4], uint32_t a0, uint32_t a1,
                                         uint32_t a2, uint32_t a3,
                                         uint32_t b0, uint32_t b1) {
    asm volatile(
        "mma.sync.aligned.m16n8k8.row.col.f32.tf32.tf32.f32 "
        "{%0,%1,%2,%3}, {%4,%5,%6,%7}, {%8,%9}, {%0,%1,%2,%3};"
        : "+f"(c[0]), "+f"(c[1]), "+f"(c[2]), "+f"(c[3])
        : "r"(a0), "r"(a1), "r"(a2), "r"(a3), "r"(b0), "r"(b1));
}
__device__ __forceinline__ float gatef(float g) {
    float sg = __fdividef(g, 1.0f + __expf(-g)) * (1.0f / 0.6f);
    return 1.0f + tanh_fast(sg);
}

// ================= kernel 1: zero ref accumulators (small) =================
__global__ void k_zacc(int n_acc4) {
    float4* acc4 = (float4*)g_ref_accum;
    int i = blockIdx.x * blockDim.x + threadIdx.x;
    if (i < n_acc4) acc4[i] = make_float4(0.f, 0.f, 0.f, 0.f);
}

// ================= kernel 2: segment-sum of edge_udiff over i =================
__global__ void k_refaccum(const float* __restrict__ ud,
                           const int* __restrict__ eidx, int E) {
    int e = blockIdx.x * blockDim.x + threadIdx.x;
    if (e >= E) return;
    int i = eidx[E + e];
    red4(&g_ref_accum[i * 4], ud[e * 3 + 0], ud[e * 3 + 1], ud[e * 3 + 2], 1.0f);
}

// ================= kernel 3: normalize ref vector per node =================
__global__ void k_refvec(int N) {
    int n = blockIdx.x * blockDim.x + threadIdx.x;
    if (n >= N) return;
    float4 a = *(const float4*)&g_ref_accum[n * 4];
    float ic = 1.0f / fmaxf(a.w, 1.0f);
    float rx = a.x * ic, ry = a.y * ic, rz = a.z * ic;
    float norm = sqrtf(rx * rx + ry * ry + rz * rz + 1e-9f);
    float inm = 1.0f / norm;
    rx *= inm; ry *= inm; rz *= inm;
    if (norm < 5e-5f) { rx = 1.0f; ry = 0.0f; rz = 0.0f; }
    g_ref_vec[n * 3 + 0] = rx;
    g_ref_vec[n * 3 + 1] = ry;
    g_ref_vec[n * 3 + 2] = rz;
}

// ================= spherical-harmonic invariants (streamed) =================
__device__ __forceinline__ void sh_invariants(
    float xe, float ye, float ze, float xr, float yr, float zr, float* inv) {
    float nne = rsqrtf(xe * xe + ye * ye + ze * ze + 1e-12f);
    xe *= nne; ye *= nne; ze *= nne;
    float nnr = rsqrtf(xr * xr + yr * yr + zr * zr + 1e-12f);
    xr *= nnr; yr *= nnr; zr *= nnr;
    float st2e = xe * xe + ye * ye;
    float st2r = xr * xr + yr * yr;
    float ste = sqrtf(st2e), str = sqrtf(st2r);
    float c1e = (st2e > 0.0f) ? xe / ste : 0.0f;
    float s1e = (st2e > 0.0f) ? ye / ste : 0.0f;
    float c1r = (st2r > 0.0f) ? xr / str : 0.0f;
    float s1r = (st2r > 0.0f) ? yr / str : 0.0f;

    float acc[7];
#pragma unroll
    for (int l = 0; l < 7; l++) acc[l] = 0.0f;

    float de = 0.28209479177387814f, dr = 0.28209479177387814f;
    float ce = 1.0f, se = 0.0f, cr = 1.0f, sr = 0.0f;
#pragma unroll
    for (int m = 0; m <= 6; m++) {
        if (m > 0) {
            float km = sqrtf((2.0f * m + 1.0f) / (2.0f * m));
            de = -km * ste * de;
            dr = -km * str * dr;
            float ce2 = c1e * ce - s1e * se; se = s1e * ce + c1e * se; ce = ce2;
            float cr2 = c1r * cr - s1r * sr; sr = s1r * cr + c1r * sr; cr = cr2;
        }
        float w = (m == 0) ? 1.0f : 2.0f * (ce * cr + se * sr);
        float pe1 = de, pr1 = dr;
        acc[m] += w * pe1 * pr1;
        if (m < 6) {
            float kp = sqrtf(2.0f * m + 3.0f);
            float pe = kp * ze * de;
            float pr = kp * zr * dr;
            acc[m + 1] += w * pe * pr;
            float pe0 = pe1, pr0 = pr1;
#pragma unroll
            for (int l = m + 2; l <= 6; l++) {
                float fl = (float)l;
                float a = sqrtf((4.0f * fl * fl - 1.0f) / (fl * fl - (float)(m * m)));
                float b = sqrtf(((fl - 1.0f) * (fl - 1.0f) - (float)(m * m)) /
                                (4.0f * (fl - 1.0f) * (fl - 1.0f) - 1.0f));
                float pen = a * (ze * pe - b * pe0); pe0 = pe; pe = pen;
                float prn = a * (zr * pr - b * pr0); pr0 = pr; pr = prn;
                acc[l] += w * pe * pr;
            }
        }
    }
    const float fourpi = 12.566370614359172f;
#pragma unroll
    for (int l = 0; l < 7; l++) inv[l] = acc[l] * (fourpi / (2.0f * l + 1.0f));
}

// ====== kernel 4: fused pre-work — roles by block range (all independent) ======
//   blocks [0, GB)           : geom (per-edge geometric features)
//   blocks [GB, GB+SB)       : sproj (node scalar MLP)
//   blocks [GB+SB, GB+SB+ZB) : zero d_out
#define GB 1563
#define SB 888
#define ZB 400

__global__ void __launch_bounds__(256)
k_pre(const float* __restrict__ ud, const int* __restrict__ eidx,
      const float* __restrict__ ln_g, const float* __restrict__ ln_b,
      const float* __restrict__ ns, const float* __restrict__ W1,
      const float* __restrict__ b1, const float* __restrict__ W2,
      const float* __restrict__ b2,
      float4* __restrict__ out4, int n_out4, int N, int E) {
    __shared__ float sW1[64 * 32];
    __shared__ float sW2[32 * 192];
    int tid = threadIdx.x;
    int bid = blockIdx.x;

    if (bid < GB) {
        // ---------------- geom role ----------------
        int e = bid * 256 + tid;
        if (e >= E) return;
        float ux = ud[e * 3 + 0], uy = ud[e * 3 + 1], uz = ud[e * 3 + 2];
        int i = __ldg(&eidx[E + e]);
        float rx = __ldg(&g_ref_vec[i * 3 + 0]);
        float ry = __ldg(&g_ref_vec[i * 3 + 1]);
        float rz = __ldg(&g_ref_vec[i * 3 + 2]);
        float inv[7];
        sh_invariants(ux, uy, uz, rx, ry, rz, inv);
        float mu = 0.0f;
#pragma unroll
        for (int l = 0; l < 7; l++) mu += inv[l];
        mu *= (1.0f / 7.0f);
        float var = 0.0f;
#pragma unroll
        for (int l = 0; l < 7; l++) { float d = inv[l] - mu; var += d * d; }
        var *= (1.0f / 7.0f);
        float isd = rsqrtf(var + 1e-5f);
        float o[8];
        o[0] = ux * rx + uy * ry + uz * rz;
#pragma unroll
        for (int l = 0; l < 7; l++)
            o[1 + l] = (inv[l] - mu) * isd * ln_g[l] + ln_b[l];
        float4* gg = (float4*)(g_geom + (size_t)e * 8);
        gg[0] = make_float4(o[0], o[1], o[2], o[3]);
        gg[1] = make_float4(o[4], o[5], o[6], o[7]);
        return;
    }
    if (bid >= GB + SB) {
        // ---------------- zero-out role ----------------
        int zb = bid - GB - SB;
        float4 z = make_float4(0.f, 0.f, 0.f, 0.f);
        for (int i = zb * 256 + tid; i < n_out4; i += ZB * 256) out4[i] = z;
        return;
    }

    // ---------------- sproj role ----------------
    int sbid = bid - GB;
    for (int q = tid; q < 64 * 32; q += 256) sW1[q] = W1[q];
    for (int q = tid; q < 32 * 192; q += 256) sW2[q] = W2[q];
    __syncthreads();
    const u64* sW2u = (const u64*)sW2;
    const float2* b2p = (const float2*)b2;
    int lane = tid & 31, warp = tid >> 5;

    u64 bb[3];
#pragma unroll
    for (int k = 0; k < 3; k++) {
        float2 t = b2p[lane + 32 * k];
        bb[k] = pk2(t.x, t.y);
    }
    float b1v = b1[lane];

    int npairs = (N + 1) >> 1;
    for (int p = sbid * 8 + warp; p < npairs; p += SB * 8) {
        int nA = p * 2;
        int nB = min(nA + 1, N - 1);
        float aA0 = ns[(size_t)nA * 64 + lane], aA1 = ns[(size_t)nA * 64 + 32 + lane];
        float aB0 = ns[(size_t)nB * 64 + lane], aB1 = ns[(size_t)nB * 64 + 32 + lane];
        float tA = b1v, tB = b1v;
#pragma unroll
        for (int r = 0; r < 64; r++) {
            float w = sW1[r * 32 + lane];
            float vA = __shfl_sync(0xffffffffu, (r < 32) ? aA0 : aA1, r & 31);
            float vB = __shfl_sync(0xffffffffu, (r < 32) ? aB0 : aB1, r & 31);
            tA = fmaf(vA, w, tA);
            tB = fmaf(vB, w, tB);
        }
        tA = __fdividef(tA, 1.0f + __expf(-tA)) * (1.0f / 0.6f);
        tB = __fdividef(tB, 1.0f + __expf(-tB)) * (1.0f / 0.6f);
        u64 oA[3], oB[3];
#pragma unroll
        for (int k = 0; k < 3; k++) { oA[k] = bb[k]; oB[k] = bb[k]; }
#pragma unroll
        for (int r = 0; r < 32; r++) {
            u64 w0 = sW2u[r * 96 + lane];
            u64 w1 = sW2u[r * 96 + 32 + lane];
            u64 w2 = sW2u[r * 96 + 64 + lane];
            float vA = __shfl_sync(0xffffffffu, tA, r);
            float vB = __shfl_sync(0xffffffffu, tB, r);
            u64 vvA = pk2(vA, vA), vvB = pk2(vB, vB);
            oA[0] = ffma2(vvA, w0, oA[0]);
            oA[1] = ffma2(vvA, w1, oA[1]);
            oA[2] = ffma2(vvA, w2, oA[2]);
            oB[0] = ffma2(vvB, w0, oB[0]);
            oB[1] = ffma2(vvB, w1, oB[1]);
            oB[2] = ffma2(vvB, w2, oB[2]);
        }
        u64* outA = (u64*)g_sproj + (size_t)nA * 96;
#pragma unroll
        for (int k = 0; k < 3; k++) outA[lane + 32 * k] = oA[k];
        if (nB != nA) {
            u64* outB = (u64*)g_sproj + (size_t)nB * 96;
#pragma unroll
            for (int k = 0; k < 3; k++) outB[lane + 32 * k] = oB[k];
        }
    }
}

// ================= kernel 5: tf32 MMA GEMM + fused gate epilogue =================
// Persistent CTAs, 256 threads = 8 warps (4 m-warps x 2 n-warps).
// Tile: 64 edges x 192 cols, K = 64. Warp: 16 edges x 96 cols (12 mma n-blocks).
__global__ void __launch_bounds__(256, 2)
k_gemm(const float* __restrict__ rbf, const int* __restrict__ eidx,
       const float* __restrict__ W_edge, const float* __restrict__ b_edge,
       const float* __restrict__ W_inv, const float* __restrict__ b_inv,
       int E) {
    extern __shared__ float sm[];
    float* sB  = sm;               // 192*68 (tf32 bits, n-major, padded)
    float* sA  = sB + 192 * 68;    // 64*68  (tf32 bits, row-major, padded)
    float* sG  = sA + 64 * 68;     // 64*8 geom
    float* sWi = sG + 512;         // 8*192 W_inv
    float* sBe = sWi + 1536;       // 192
    float* sBi = sBe + 192;        // 192
    int*   sJ  = (int*)(sBi + 192);  // 64

    int tid = threadIdx.x;
    int lane = tid & 31, warp = tid >> 5;
    int wm = warp >> 1, wn = warp & 1;
    int gid = lane >> 2, tig = lane & 3;

    // persistent staging: B=W_edge (tf32), W_inv, biases
    for (int i = tid; i < 64 * 192; i += 256) {
        int k = i / 192, n = i - k * 192;
        ((uint32_t*)sB)[n * 68 + k] = f2tf32(W_edge[i]);
    }
    for (int i = tid; i < 8 * 192; i += 256) sWi[i] = W_inv[i];
    if (tid < 192) { sBe[tid] = b_edge[tid]; sBi[tid] = b_inv[tid]; }

    const u64* sWi64 = (const u64*)sWi;
    const float2* sBe2 = (const float2*)sBe;
    const float2* sBi2 = (const float2*)sBi;
    const uint32_t* uA = (const uint32_t*)sA;
    const uint32_t* uB = (const uint32_t*)sB;

    int r0 = wm * 16 + gid;
    int nb_base = wn * 96;
    const float inv_sqrt3 = 0.57735026918962576f;

    int ntiles = (E + GTE - 1) / GTE;
    for (int t = blockIdx.x; t < ntiles; t += gridDim.x) {
        int e0 = t * GTE;
        __syncthreads();  // staging buffers free (also covers first-iter staging)

        // stage A tile (cvt to tf32)
        for (int i = tid; i < 64 * 16; i += 256) {
            int r = i >> 4, c4 = i & 15;
            int e = min(e0 + r, E - 1);
            float4 v = __ldg((const float4*)(rbf + (size_t)e * 64 + c4 * 4));
            uint4 u;
            u.x = f2tf32(v.x); u.y = f2tf32(v.y);
            u.z = f2tf32(v.z); u.w = f2tf32(v.w);
            *(uint4*)(sA + r * 68 + c4 * 4) = u;
        }
        // stage geom + j-index
        if (tid < 128) {
            int e = min(e0 + (tid >> 1), E - 1);
            ((float4*)sG)[tid] =
                __ldg((const float4*)(g_geom + (size_t)e * 8) + (tid & 1));
        }
        if (tid < 64) sJ[tid] = __ldg(&eidx[min(e0 + tid, E - 1)]);
        __syncthreads();

        // ---- MMA mainloop ----
        float acc[12][4];
#pragma unroll
        for (int nb = 0; nb < 12; nb++)
            acc[nb][0] = acc[nb][1] = acc[nb][2] = acc[nb][3] = 0.0f;
#pragma unroll
        for (int kc = 0; kc < 8; kc++) {
            int k0 = kc * 8 + tig;
            uint32_t a0 = uA[r0 * 68 + k0];
            uint32_t a1 = uA[(r0 + 8) * 68 + k0];
            uint32_t a2 = uA[r0 * 68 + k0 + 4];
            uint32_t a3 = uA[(r0 + 8) * 68 + k0 + 4];
#pragma unroll
            for (int nb = 0; nb < 12; nb++) {
                int n = nb_base + nb * 8 + gid;
                uint32_t b0 = uB[n * 68 + k0];
                uint32_t b1 = uB[n * 68 + k0 + 4];
                mma_tf32(acc[nb], a0, a1, a2, a3, b0, b1);
            }
        }

        // ---- fused epilogue: gate + bias + sproj, per (edge,col) element ----
        u64 gr0[8], gr1[8];
#pragma unroll
        for (int q = 0; q < 8; q++) {
            float v0 = sG[r0 * 8 + q], v1 = sG[(r0 + 8) * 8 + q];
            gr0[q] = pk2(v0, v0);
            gr1[q] = pk2(v1, v1);
        }
        int j0 = sJ[r0], j1 = sJ[r0 + 8];
        bool val0 = (e0 + r0) < E, val1 = (e0 + r0 + 8) < E;
        __half* xrow0 = g_x + (size_t)(e0 + r0) * 192;
        __half* xrow1 = g_x + (size_t)(e0 + r0 + 8) * 192;
#pragma unroll
        for (int nb = 0; nb < 12; nb++) {
            int col = nb_base + nb * 8 + tig * 2;
            int ch = col >> 1;
            u64 g0 = 0ull, g1 = 0ull;
#pragma unroll
            for (int q = 0; q < 8; q++) {
                u64 w = sWi64[q * 96 + ch];
                g0 = ffma2(gr0[q], w, g0);
                g1 = ffma2(gr1[q], w, g1);
            }
            float2 bi = sBi2[ch];
            float2 be = sBe2[ch];
            float g00, g01, g10, g11;
            upk2(g0, g00, g01);
            upk2(g1, g10, g11);
            float f00 = gatef(g00 + bi.x), f01 = gatef(g01 + bi.y);
            float f10 = gatef(g10 + bi.x), f11 = gatef(g11 + bi.y);
            float2 sp0 = __ldg((const float2*)(g_sproj + (size_t)j0 * 192 + col));
            float2 sp1 = __ldg((const float2*)(g_sproj + (size_t)j1 * 192 + col));
            float x00 = sp0.x * (acc[nb][0] + be.x) * f00 * inv_sqrt3;
            float x01 = sp0.y * (acc[nb][1] + be.y) * f01 * inv_sqrt3;
            float x10 = sp1.x * (acc[nb][2] + be.x) * f10 * inv_sqrt3;
            float x11 = sp1.y * (acc[nb][3] + be.y) * f11 * inv_sqrt3;
            if (val0) *(__half2*)(xrow0 + col) = __floats2half2_rn(x00, x01);
            if (val1) *(__half2*)(xrow1 + col) = __floats2half2_rn(x10, x11);
        }
    }
}

// ================= kernel 6: scatter (warp per edge) =================
__global__ void __launch_bounds__(256)
k_scatter(const float* __restrict__ ud, const int* __restrict__ eidx,
          const float* __restrict__ nv, float* __restrict__ out, int N, int E) {
    __shared__ __align__(16) float sX[8][192];
    int lane = threadIdx.x & 31, warp = threadIdx.x >> 5;
    float* xf = sX[warp];
    float* outv = out + (size_t)N * 64;
    const float ish = 0.125f;

    for (int e = blockIdx.x * 8 + warp; e < E; e += gridDim.x * 8) {
        const __half2* xr = (const __half2*)(g_x + (size_t)e * 192);
        float2 v0 = __half22float2(__ldg(xr + lane));        // x1
        float2 v1 = __half22float2(__ldg(xr + 32 + lane));   // x2
        float2 v2 = __half22float2(__ldg(xr + 64 + lane));   // x3
        ((float2*)xf)[lane] = v0;
        ((float2*)xf)[32 + lane] = v1;
        ((float2*)xf)[64 + lane] = v2;
        int j = __ldg(&eidx[e]), in = __ldg(&eidx[E + e]);
        float ud0 = __ldg(&ud[e * 3 + 0]);
        float ud1 = __ldg(&ud[e * 3 + 1]);
        float ud2 = __ldg(&ud[e * 3 + 2]);
        __syncwarp();

        if (lane < 16) {  // delta_scalar: x3
            const float4 x3v = *(const float4*)&xf[128 + 4 * lane];
            red4(&out[(size_t)in * 64 + 4 * lane], x3v.x, x3v.y, x3v.z, x3v.w);
        }
        {  // delta_vector d=0,1: o = 4*lane in [0,128)
            int o = 4 * lane;
            float udd = (o >> 6) ? ud1 : ud0;
            int h = o & 63;
            const float4 f1 = *(const float4*)&xf[h];
            const float4 f2 = *(const float4*)&xf[64 + h];
            float4 nvv = __ldg((const float4*)(nv + (size_t)j * 192 + o));
            red4(&outv[(size_t)in * 192 + o],
                 (f1.x * nvv.x + f2.x * udd) * ish,
                 (f1.y * nvv.y + f2.y * udd) * ish,
                 (f1.z * nvv.z + f2.z * udd) * ish,
                 (f1.w * nvv.w + f2.w * udd) * ish);
        }
        if (lane < 16) {  // delta_vector d=2
            int o = 128 + 4 * lane;
            int h = 4 * lane;
            const float4 f1 = *(const float4*)&xf[h];
            const float4 f2 = *(const float4*)&xf[64 + h];
            float4 nvv = __ldg((const float4*)(nv + (size_t)j * 192 + o));
            red4(&outv[(size_t)in * 192 + o],
                 (f1.x * nvv.x + f2.x * ud2) * ish,
                 (f1.y * nvv.y + f2.y * ud2) * ish,
                 (f1.z * nvv.z + f2.z * ud2) * ish,
                 (f1.w * nvv.w + f2.w * ud2) * ish);
        }
        __syncwarp();
    }
}

// ================= launch =================
extern "C" void kernel_launch(void* const* d_in, const int* in_sizes, int n_in,
                              void* d_out, int out_size) {
    const float* node_scalar = (const float*)d_in[0];
    const float* node_vector = (const float*)d_in[1];
    const float* edge_rbf    = (const float*)d_in[2];
    const float* edge_udiff  = (const float*)d_in[3];
    const int*   edge_index  = (const int*)d_in[4];
    const float* W_edge      = (const float*)d_in[5];
    const float* b_edge      = (const float*)d_in[6];
    const float* W_x1        = (const float*)d_in[7];
    const float* b_x1        = (const float*)d_in[8];
    const float* W_x2        = (const float*)d_in[9];
    const float* b_x2        = (const float*)d_in[10];
    const float* ln_g        = (const float*)d_in[11];
    const float* ln_b        = (const float*)d_in[12];
    const float* W_inv       = (const float*)d_in[13];
    const float* b_inv       = (const float*)d_in[14];

    int N = in_sizes[0] / 64;
    int E = in_sizes[3] / 3;
    float* out = (float*)d_out;

    // dynamic smem for k_gemm: B + A + geom + W_inv + biases + J
    int smem_gemm = (192 * 68 + 64 * 68 + 512 + 1536 + 192 + 192) * 4 + 64 * 4;
    cudaFuncSetAttribute(k_gemm, cudaFuncAttributeMaxDynamicSharedMemorySize,
                         smem_gemm);

    k_zacc<<<(N * 4 / 4 + 255) / 256, 256>>>(N);  // N float4 accumulators
    k_refaccum<<<(E + 255) / 256, 256>>>(edge_udiff, edge_index, E);
    k_refvec<<<(N + 255) / 256, 256>>>(N);
    // fused independent pre-work: geom + sproj + zero-out, co-scheduled
    k_pre<<<GB + SB + ZB, 256>>>(edge_udiff, edge_index, ln_g, ln_b,
                                 node_scalar, W_x1, b_x1, W_x2, b_x2,
                                 (float4*)out, out_size / 4, N, E);
    k_gemm<<<296, 256, smem_gemm>>>(edge_rbf, edge_index, W_edge, b_edge,
                                    W_inv, b_inv, E);
    k_scatter<<<2960, 256>>>(edge_udiff, edge_index, node_vector, out, N, E);
}

// round 11
// speedup vs baseline: 1.4833x; 1.0437x over previous
#include <cuda_runtime.h>
#include <cuda_fp16.h>
#include <math.h>
#include <stdint.h>

#define NMAX 50000
#define EMAX 400000
#define GTE 64   // edges per gemm tile

// ---- scratch (device globals; no allocation allowed) ----
__device__ float g_ref_accum[NMAX * 4];   // sum x,y,z + count
__device__ __half2 g_sproj_h[(size_t)NMAX * 96];  // fp16 node projections
__device__ float g_geom[(size_t)EMAX * 8];
__device__ __half g_x[(size_t)EMAX * 192];  // gated per-edge messages (fp16)

// ---------------- helpers ----------------
typedef unsigned long long u64;
__device__ __forceinline__ u64 pk2(float lo, float hi) {
    u64 r;
    asm("mov.b64 %0, {%1, %2};" : "=l"(r) : "f"(lo), "f"(hi));
    return r;
}
__device__ __forceinline__ void upk2(u64 v, float& lo, float& hi) {
    asm("mov.b64 {%0, %1}, %2;" : "=f"(lo), "=f"(hi) : "l"(v));
}
__device__ __forceinline__ u64 ffma2(u64 a, u64 b, u64 c) {
    u64 d;
    asm("fma.rn.f32x2 %0, %1, %2, %3;" : "=l"(d) : "l"(a), "l"(b), "l"(c));
    return d;
}
__device__ __forceinline__ float tanh_fast(float x) {
    float y;
    asm("tanh.approx.f32 %0, %1;" : "=f"(y) : "f"(x));
    return y;
}
__device__ __forceinline__ void red4(float* a, float x, float y, float z, float w) {
    asm volatile("red.global.add.v4.f32 [%0], {%1, %2, %3, %4};"
                 :: "l"(a), "f"(x), "f"(y), "f"(z), "f"(w) : "memory");
}
__device__ __forceinline__ uint32_t f2tf32(float v) {
    uint32_t t;
    asm("cvt.rna.tf32.f32 %0, %1;" : "=r"(t) : "f"(v));
    return t;
}
__device__ __forceinline__ void mma_tf32(float c[4], uint32_t a0, uint32_t a1,
                                         uint32_t a2, uint32_t a3,
                                         uint32_t b0, uint32_t b1) {
    asm volatile(
        "mma.sync.aligned.m16n8k8.row.col.f32.tf32.tf32.f32 "
        "{%0,%1,%2,%3}, {%4,%5,%6,%7}, {%8,%9}, {%0,%1,%2,%3};"
        : "+f"(c[0]), "+f"(c[1]), "+f"(c[2]), "+f"(c[3])
        : "r"(a0), "r"(a1), "r"(a2), "r"(a3), "r"(b0), "r"(b1));
}
// gate = 1 + tanh(silu(g)/0.6); silu via sigmoid(g) = 0.5*(1+tanh(g/2))
// -> 2 MUFU total, no exp / no divide.
__device__ __forceinline__ float gatef(float g) {
    float t = tanh_fast(g * 0.5f);
    float sg = g * (1.0f + t) * (0.5f / 0.6f);
    return 1.0f + tanh_fast(sg);
}

// ================= kernel 1: zero ref accumulators (small) =================
__global__ void k_zacc(int n_acc4) {
    float4* acc4 = (float4*)g_ref_accum;
    int i = blockIdx.x * blockDim.x + threadIdx.x;
    if (i < n_acc4) acc4[i] = make_float4(0.f, 0.f, 0.f, 0.f);
}

// ================= kernel 2: segment-sum of edge_udiff over i =================
__global__ void k_refaccum(const float* __restrict__ ud,
                           const int* __restrict__ eidx, int E) {
    int e = blockIdx.x * blockDim.x + threadIdx.x;
    if (e >= E) return;
    int i = eidx[E + e];
    red4(&g_ref_accum[i * 4], ud[e * 3 + 0], ud[e * 3 + 1], ud[e * 3 + 2], 1.0f);
}

// ================= spherical-harmonic invariants (streamed) =================
__device__ __forceinline__ void sh_invariants(
    float xe, float ye, float ze, float xr, float yr, float zr, float* inv) {
    float nne = rsqrtf(xe * xe + ye * ye + ze * ze + 1e-12f);
    xe *= nne; ye *= nne; ze *= nne;
    float nnr = rsqrtf(xr * xr + yr * yr + zr * zr + 1e-12f);
    xr *= nnr; yr *= nnr; zr *= nnr;
    float st2e = xe * xe + ye * ye;
    float st2r = xr * xr + yr * yr;
    float ste = sqrtf(st2e), str = sqrtf(st2r);
    float c1e = (st2e > 0.0f) ? xe / ste : 0.0f;
    float s1e = (st2e > 0.0f) ? ye / ste : 0.0f;
    float c1r = (st2r > 0.0f) ? xr / str : 0.0f;
    float s1r = (st2r > 0.0f) ? yr / str : 0.0f;

    float acc[7];
#pragma unroll
    for (int l = 0; l < 7; l++) acc[l] = 0.0f;

    float de = 0.28209479177387814f, dr = 0.28209479177387814f;
    float ce = 1.0f, se = 0.0f, cr = 1.0f, sr = 0.0f;
#pragma unroll
    for (int m = 0; m <= 6; m++) {
        if (m > 0) {
            float km = sqrtf((2.0f * m + 1.0f) / (2.0f * m));
            de = -km * ste * de;
            dr = -km * str * dr;
            float ce2 = c1e * ce - s1e * se; se = s1e * ce + c1e * se; ce = ce2;
            float cr2 = c1r * cr - s1r * sr; sr = s1r * cr + c1r * sr; cr = cr2;
        }
        float w = (m == 0) ? 1.0f : 2.0f * (ce * cr + se * sr);
        float pe1 = de, pr1 = dr;
        acc[m] += w * pe1 * pr1;
        if (m < 6) {
            float kp = sqrtf(2.0f * m + 3.0f);
            float pe = kp * ze * de;
            float pr = kp * zr * dr;
            acc[m + 1] += w * pe * pr;
            float pe0 = pe1, pr0 = pr1;
#pragma unroll
            for (int l = m + 2; l <= 6; l++) {
                float fl = (float)l;
                float a = sqrtf((4.0f * fl * fl - 1.0f) / (fl * fl - (float)(m * m)));
                float b = sqrtf(((fl - 1.0f) * (fl - 1.0f) - (float)(m * m)) /
                                (4.0f * (fl - 1.0f) * (fl - 1.0f) - 1.0f));
                float pen = a * (ze * pe - b * pe0); pe0 = pe; pe = pen;
                float prn = a * (zr * pr - b * pr0); pr0 = pr; pr = prn;
                acc[l] += w * pe * pr;
            }
        }
    }
    const float fourpi = 12.566370614359172f;
#pragma unroll
    for (int l = 0; l < 7; l++) inv[l] = acc[l] * (fourpi / (2.0f * l + 1.0f));
}

// ====== kernel 3: fused pre-work — roles by block range (all independent) ======
//   blocks [0, GB)           : geom (inline ref-vec normalize + SH invariants)
//   blocks [GB, GB+SB)       : sproj (node scalar MLP, fp16 output)
//   blocks [GB+SB, GB+SB+ZB) : zero d_out
#define GB 1563
#define SB 888
#define ZB 400

__global__ void __launch_bounds__(256)
k_pre(const float* __restrict__ ud, const int* __restrict__ eidx,
      const float* __restrict__ ln_g, const float* __restrict__ ln_b,
      const float* __restrict__ ns, const float* __restrict__ W1,
      const float* __restrict__ b1, const float* __restrict__ W2,
      const float* __restrict__ b2,
      float4* __restrict__ out4, int n_out4, int N, int E) {
    __shared__ float sW1[64 * 32];
    __shared__ float sW2[32 * 192];
    int tid = threadIdx.x;
    int bid = blockIdx.x;

    if (bid < GB) {
        // ---------------- geom role (ref-vec normalize folded in) ----------
        int e = bid * 256 + tid;
        if (e >= E) return;
        float ux = ud[e * 3 + 0], uy = ud[e * 3 + 1], uz = ud[e * 3 + 2];
        int i = __ldg(&eidx[E + e]);
        float4 a = *(const float4*)&g_ref_accum[i * 4];
        float ic = 1.0f / fmaxf(a.w, 1.0f);
        float rx = a.x * ic, ry = a.y * ic, rz = a.z * ic;
        float norm = sqrtf(rx * rx + ry * ry + rz * rz + 1e-9f);
        float inm = 1.0f / norm;
        rx *= inm; ry *= inm; rz *= inm;
        if (norm < 5e-5f) { rx = 1.0f; ry = 0.0f; rz = 0.0f; }

        float inv[7];
        sh_invariants(ux, uy, uz, rx, ry, rz, inv);
        float mu = 0.0f;
#pragma unroll
        for (int l = 0; l < 7; l++) mu += inv[l];
        mu *= (1.0f / 7.0f);
        float var = 0.0f;
#pragma unroll
        for (int l = 0; l < 7; l++) { float d = inv[l] - mu; var += d * d; }
        var *= (1.0f / 7.0f);
        float isd = rsqrtf(var + 1e-5f);
        float o[8];
        o[0] = ux * rx + uy * ry + uz * rz;
#pragma unroll
        for (int l = 0; l < 7; l++)
            o[1 + l] = (inv[l] - mu) * isd * ln_g[l] + ln_b[l];
        float4* gg = (float4*)(g_geom + (size_t)e * 8);
        gg[0] = make_float4(o[0], o[1], o[2], o[3]);
        gg[1] = make_float4(o[4], o[5], o[6], o[7]);
        return;
    }
    if (bid >= GB + SB) {
        // ---------------- zero-out role ----------------
        int zb = bid - GB - SB;
        float4 z = make_float4(0.f, 0.f, 0.f, 0.f);
        for (int i = zb * 256 + tid; i < n_out4; i += ZB * 256) out4[i] = z;
        return;
    }

    // ---------------- sproj role (fp16 output) ----------------
    int sbid = bid - GB;
    for (int q = tid; q < 64 * 32; q += 256) sW1[q] = W1[q];
    for (int q = tid; q < 32 * 192; q += 256) sW2[q] = W2[q];
    __syncthreads();
    const u64* sW2u = (const u64*)sW2;
    const float2* b2p = (const float2*)b2;
    int lane = tid & 31, warp = tid >> 5;

    u64 bb[3];
#pragma unroll
    for (int k = 0; k < 3; k++) {
        float2 t = b2p[lane + 32 * k];
        bb[k] = pk2(t.x, t.y);
    }
    float b1v = b1[lane];

    int npairs = (N + 1) >> 1;
    for (int p = sbid * 8 + warp; p < npairs; p += SB * 8) {
        int nA = p * 2;
        int nB = min(nA + 1, N - 1);
        float aA0 = ns[(size_t)nA * 64 + lane], aA1 = ns[(size_t)nA * 64 + 32 + lane];
        float aB0 = ns[(size_t)nB * 64 + lane], aB1 = ns[(size_t)nB * 64 + 32 + lane];
        float tA = b1v, tB = b1v;
#pragma unroll
        for (int r = 0; r < 64; r++) {
            float w = sW1[r * 32 + lane];
            float vA = __shfl_sync(0xffffffffu, (r < 32) ? aA0 : aA1, r & 31);
            float vB = __shfl_sync(0xffffffffu, (r < 32) ? aB0 : aB1, r & 31);
            tA = fmaf(vA, w, tA);
            tB = fmaf(vB, w, tB);
        }
        tA = __fdividef(tA, 1.0f + __expf(-tA)) * (1.0f / 0.6f);
        tB = __fdividef(tB, 1.0f + __expf(-tB)) * (1.0f / 0.6f);
        u64 oA[3], oB[3];
#pragma unroll
        for (int k = 0; k < 3; k++) { oA[k] = bb[k]; oB[k] = bb[k]; }
#pragma unroll
        for (int r = 0; r < 32; r++) {
            u64 w0 = sW2u[r * 96 + lane];
            u64 w1 = sW2u[r * 96 + 32 + lane];
            u64 w2 = sW2u[r * 96 + 64 + lane];
            float vA = __shfl_sync(0xffffffffu, tA, r);
            float vB = __shfl_sync(0xffffffffu, tB, r);
            u64 vvA = pk2(vA, vA), vvB = pk2(vB, vB);
            oA[0] = ffma2(vvA, w0, oA[0]);
            oA[1] = ffma2(vvA, w1, oA[1]);
            oA[2] = ffma2(vvA, w2, oA[2]);
            oB[0] = ffma2(vvB, w0, oB[0]);
            oB[1] = ffma2(vvB, w1, oB[1]);
            oB[2] = ffma2(vvB, w2, oB[2]);
        }
        __half2* outA = g_sproj_h + (size_t)nA * 96;
#pragma unroll
        for (int k = 0; k < 3; k++) {
            float lo, hi; upk2(oA[k], lo, hi);
            outA[lane + 32 * k] = __floats2half2_rn(lo, hi);
        }
        if (nB != nA) {
            __half2* outB = g_sproj_h + (size_t)nB * 96;
#pragma unroll
            for (int k = 0; k < 3; k++) {
                float lo, hi; upk2(oB[k], lo, hi);
                outB[lane + 32 * k] = __floats2half2_rn(lo, hi);
            }
        }
    }
}

// ================= kernel 4: tf32 MMA GEMM + fused gate epilogue =================
// Persistent CTAs, 256 threads = 8 warps (4 m-warps x 2 n-warps).
// Tile: 64 edges x 192 cols, K = 64. Warp: 16 edges x 96 cols (12 mma n-blocks).
__global__ void __launch_bounds__(256, 2)
k_gemm(const float* __restrict__ rbf, const int* __restrict__ eidx,
       const float* __restrict__ W_edge, const float* __restrict__ b_edge,
       const float* __restrict__ W_inv, const float* __restrict__ b_inv,
       int E) {
    extern __shared__ float sm[];
    float* sB  = sm;               // 192*68 (tf32 bits, n-major, padded)
    float* sA  = sB + 192 * 68;    // 64*68  (tf32 bits, row-major, padded)
    float* sG  = sA + 64 * 68;     // 64*8 geom
    float* sWi = sG + 512;         // 8*192 W_inv
    float* sBe = sWi + 1536;       // 192
    float* sBi = sBe + 192;        // 192
    int*   sJ  = (int*)(sBi + 192);  // 64

    int tid = threadIdx.x;
    int lane = tid & 31, warp = tid >> 5;
    int wm = warp >> 1, wn = warp & 1;
    int gid = lane >> 2, tig = lane & 3;

    // persistent staging: B=W_edge (tf32), W_inv, biases
    for (int i = tid; i < 64 * 192; i += 256) {
        int k = i / 192, n = i - k * 192;
        ((uint32_t*)sB)[n * 68 + k] = f2tf32(W_edge[i]);
    }
    for (int i = tid; i < 8 * 192; i += 256) sWi[i] = W_inv[i];
    if (tid < 192) { sBe[tid] = b_edge[tid]; sBi[tid] = b_inv[tid]; }

    const u64* sWi64 = (const u64*)sWi;
    const float2* sBe2 = (const float2*)sBe;
    const float2* sBi2 = (const float2*)sBi;
    const uint32_t* uA = (const uint32_t*)sA;
    const uint32_t* uB = (const uint32_t*)sB;

    int r0 = wm * 16 + gid;
    int nb_base = wn * 96;
    const float inv_sqrt3 = 0.57735026918962576f;

    int ntiles = (E + GTE - 1) / GTE;
    for (int t = blockIdx.x; t < ntiles; t += gridDim.x) {
        int e0 = t * GTE;
        __syncthreads();  // staging buffers free (also covers first-iter staging)

        // stage A tile (cvt to tf32)
        for (int i = tid; i < 64 * 16; i += 256) {
            int r = i >> 4, c4 = i & 15;
            int e = min(e0 + r, E - 1);
            float4 v = __ldg((const float4*)(rbf + (size_t)e * 64 + c4 * 4));
            uint4 u;
            u.x = f2tf32(v.x); u.y = f2tf32(v.y);
            u.z = f2tf32(v.z); u.w = f2tf32(v.w);
            *(uint4*)(sA + r * 68 + c4 * 4) = u;
        }
        // stage geom + j-index
        if (tid < 128) {
            int e = min(e0 + (tid >> 1), E - 1);
            ((float4*)sG)[tid] =
                __ldg((const float4*)(g_geom + (size_t)e * 8) + (tid & 1));
        }
        if (tid < 64) sJ[tid] = __ldg(&eidx[min(e0 + tid, E - 1)]);
        __syncthreads();

        // ---- MMA mainloop ----
        float acc[12][4];
#pragma unroll
        for (int nb = 0; nb < 12; nb++)
            acc[nb][0] = acc[nb][1] = acc[nb][2] = acc[nb][3] = 0.0f;
#pragma unroll
        for (int kc = 0; kc < 8; kc++) {
            int k0 = kc * 8 + tig;
            uint32_t a0 = uA[r0 * 68 + k0];
            uint32_t a1 = uA[(r0 + 8) * 68 + k0];
            uint32_t a2 = uA[r0 * 68 + k0 + 4];
            uint32_t a3 = uA[(r0 + 8) * 68 + k0 + 4];
#pragma unroll
            for (int nb = 0; nb < 12; nb++) {
                int n = nb_base + nb * 8 + gid;
                uint32_t b0 = uB[n * 68 + k0];
                uint32_t b1 = uB[n * 68 + k0 + 4];
                mma_tf32(acc[nb], a0, a1, a2, a3, b0, b1);
            }
        }

        // ---- fused epilogue: gate + bias + sproj, per (edge,col) element ----
        u64 gr0[8], gr1[8];
#pragma unroll
        for (int q = 0; q < 8; q++) {
            float v0 = sG[r0 * 8 + q], v1 = sG[(r0 + 8) * 8 + q];
            gr0[q] = pk2(v0, v0);
            gr1[q] = pk2(v1, v1);
        }
        int j0 = sJ[r0], j1 = sJ[r0 + 8];
        bool val0 = (e0 + r0) < E, val1 = (e0 + r0 + 8) < E;
        __half* xrow0 = g_x + (size_t)(e0 + r0) * 192;
        __half* xrow1 = g_x + (size_t)(e0 + r0 + 8) * 192;
#pragma unroll
        for (int nb = 0; nb < 12; nb++) {
            int col = nb_base + nb * 8 + tig * 2;
            int ch = col >> 1;
            u64 g0 = 0ull, g1 = 0ull;
#pragma unroll
            for (int q = 0; q < 8; q++) {
                u64 w = sWi64[q * 96 + ch];
                g0 = ffma2(gr0[q], w, g0);
                g1 = ffma2(gr1[q], w, g1);
            }
            float2 bi = sBi2[ch];
            float2 be = sBe2[ch];
            float g00, g01, g10, g11;
            upk2(g0, g00, g01);
            upk2(g1, g10, g11);
            float f00 = gatef(g00 + bi.x), f01 = gatef(g01 + bi.y);
            float f10 = gatef(g10 + bi.x), f11 = gatef(g11 + bi.y);
            float2 sp0 = __half22float2(__ldg(&g_sproj_h[(size_t)j0 * 96 + ch]));
            float2 sp1 = __half22float2(__ldg(&g_sproj_h[(size_t)j1 * 96 + ch]));
            float x00 = sp0.x * (acc[nb][0] + be.x) * f00 * inv_sqrt3;
            float x01 = sp0.y * (acc[nb][1] + be.y) * f01 * inv_sqrt3;
            float x10 = sp1.x * (acc[nb][2] + be.x) * f10 * inv_sqrt3;
            float x11 = sp1.y * (acc[nb][3] + be.y) * f11 * inv_sqrt3;
            if (val0) *(__half2*)(xrow0 + col) = __floats2half2_rn(x00, x01);
            if (val1) *(__half2*)(xrow1 + col) = __floats2half2_rn(x10, x11);
        }
    }
}

// ================= kernel 5: scatter (warp per edge) =================
__global__ void __launch_bounds__(256)
k_scatter(const float* __restrict__ ud, const int* __restrict__ eidx,
          const float* __restrict__ nv, float* __restrict__ out, int N, int E) {
    __shared__ __align__(16) float sX[8][192];
    int lane = threadIdx.x & 31, warp = threadIdx.x >> 5;
    float* xf = sX[warp];
    float* outv = out + (size_t)N * 64;
    const float ish = 0.125f;

    for (int e = blockIdx.x * 8 + warp; e < E; e += gridDim.x * 8) {
        const __half2* xr = (const __half2*)(g_x + (size_t)e * 192);
        float2 v0 = __half22float2(__ldg(xr + lane));        // x1
        float2 v1 = __half22float2(__ldg(xr + 32 + lane));   // x2
        float2 v2 = __half22float2(__ldg(xr + 64 + lane));   // x3
        ((float2*)xf)[lane] = v0;
        ((float2*)xf)[32 + lane] = v1;
        ((float2*)xf)[64 + lane] = v2;
        int j = __ldg(&eidx[e]), in = __ldg(&eidx[E + e]);
        float ud0 = __ldg(&ud[e * 3 + 0]);
        float ud1 = __ldg(&ud[e * 3 + 1]);
        float ud2 = __ldg(&ud[e * 3 + 2]);
        __syncwarp();

        if (lane < 16) {  // delta_scalar: x3
            const float4 x3v = *(const float4*)&xf[128 + 4 * lane];
            red4(&out[(size_t)in * 64 + 4 * lane], x3v.x, x3v.y, x3v.z, x3v.w);
        }
        {  // delta_vector d=0,1: o = 4*lane in [0,128)
            int o = 4 * lane;
            float udd = (o >> 6) ? ud1 : ud0;
            int h = o & 63;
            const float4 f1 = *(const float4*)&xf[h];
            const float4 f2 = *(const float4*)&xf[64 + h];
            float4 nvv = __ldg((const float4*)(nv + (size_t)j * 192 + o));
            red4(&outv[(size_t)in * 192 + o],
                 (f1.x * nvv.x + f2.x * udd) * ish,
                 (f1.y * nvv.y + f2.y * udd) * ish,
                 (f1.z * nvv.z + f2.z * udd) * ish,
                 (f1.w * nvv.w + f2.w * udd) * ish);
        }
        if (lane < 16) {  // delta_vector d=2
            int o = 128 + 4 * lane;
            int h = 4 * lane;
            const float4 f1 = *(const float4*)&xf[h];
            const float4 f2 = *(const float4*)&xf[64 + h];
            float4 nvv = __ldg((const float4*)(nv + (size_t)j * 192 + o));
            red4(&outv[(size_t)in * 192 + o],
                 (f1.x * nvv.x + f2.x * ud2) * ish,
                 (f1.y * nvv.y + f2.y * ud2) * ish,
                 (f1.z * nvv.z + f2.z * ud2) * ish,
                 (f1.w * nvv.w + f2.w * ud2) * ish);
        }
        __syncwarp();
    }
}

// ================= launch =================
extern "C" void kernel_launch(void* const* d_in, const int* in_sizes, int n_in,
                              void* d_out, int out_size) {
    const float* node_scalar = (const float*)d_in[0];
    const float* node_vector = (const float*)d_in[1];
    const float* edge_rbf    = (const float*)d_in[2];
    const float* edge_udiff  = (const float*)d_in[3];
    const int*   edge_index  = (const int*)d_in[4];
    const float* W_edge      = (const float*)d_in[5];
    const float* b_edge      = (const float*)d_in[6];
    const float* W_x1        = (const float*)d_in[7];
    const float* b_x1        = (const float*)d_in[8];
    const float* W_x2        = (const float*)d_in[9];
    const float* b_x2        = (const float*)d_in[10];
    const float* ln_g        = (const float*)d_in[11];
    const float* ln_b        = (const float*)d_in[12];
    const float* W_inv       = (const float*)d_in[13];
    const float* b_inv       = (const float*)d_in[14];

    int N = in_sizes[0] / 64;
    int E = in_sizes[3] / 3;
    float* out = (float*)d_out;

    // dynamic smem for k_gemm: B + A + geom + W_inv + biases + J
    int smem_gemm = (192 * 68 + 64 * 68 + 512 + 1536 + 192 + 192) * 4 + 64 * 4;
    cudaFuncSetAttribute(k_gemm, cudaFuncAttributeMaxDynamicSharedMemorySize,
                         smem_gemm);

    k_zacc<<<(N + 255) / 256, 256>>>(N);  // N float4 accumulators
    k_refaccum<<<(E + 255) / 256, 256>>>(edge_udiff, edge_index, E);
    // fused independent pre-work: geom (incl. refvec) + sproj + zero-out
    k_pre<<<GB + SB + ZB, 256>>>(edge_udiff, edge_index, ln_g, ln_b,
                                 node_scalar, W_x1, b_x1, W_x2, b_x2,
                                 (float4*)out, out_size / 4, N, E);
    k_gemm<<<296, 256, smem_gemm>>>(edge_rbf, edge_index, W_edge, b_edge,
                                    W_inv, b_inv, E);
    k_scatter<<<2960, 256>>>(edge_udiff, edge_index, node_vector, out, N, E);
}

// round 12
// speedup vs baseline: 1.6323x; 1.1005x over previous
#include <cuda_runtime.h>
#include <cuda_fp16.h>
#include <math.h>
#include <stdint.h>

#define NMAX 50000
#define EMAX 400000
#define GTE 64   // edges per gemm tile

// ---- scratch (device globals; no allocation allowed) ----
__device__ float g_ref_accum[NMAX * 4];   // sum x,y,z + count
__device__ __half2 g_sproj_h[(size_t)NMAX * 96];  // fp16 node projections
__device__ float g_geom[(size_t)EMAX * 8];
__device__ __half g_x[(size_t)EMAX * 192];  // gated per-edge messages (fp16)

// ---------------- helpers ----------------
typedef unsigned long long u64;
__device__ __forceinline__ u64 pk2(float lo, float hi) {
    u64 r;
    asm("mov.b64 %0, {%1, %2};" : "=l"(r) : "f"(lo), "f"(hi));
    return r;
}
__device__ __forceinline__ void upk2(u64 v, float& lo, float& hi) {
    asm("mov.b64 {%0, %1}, %2;" : "=f"(lo), "=f"(hi) : "l"(v));
}
__device__ __forceinline__ u64 ffma2(u64 a, u64 b, u64 c) {
    u64 d;
    asm("fma.rn.f32x2 %0, %1, %2, %3;" : "=l"(d) : "l"(a), "l"(b), "l"(c));
    return d;
}
__device__ __forceinline__ float tanh_fast(float x) {
    float y;
    asm("tanh.approx.f32 %0, %1;" : "=f"(y) : "f"(x));
    return y;
}
__device__ __forceinline__ void red4(float* a, float x, float y, float z, float w) {
    asm volatile("red.global.add.v4.f32 [%0], {%1, %2, %3, %4};"
                 :: "l"(a), "f"(x), "f"(y), "f"(z), "f"(w) : "memory");
}
__device__ __forceinline__ uint32_t f2h2(float a, float b) {
    __half2 h = __floats2half2_rn(a, b);
    return *(uint32_t*)&h;
}
__device__ __forceinline__ void mma_f16(float c[4], uint32_t a0, uint32_t a1,
                                        uint32_t a2, uint32_t a3,
                                        uint32_t b0, uint32_t b1) {
    asm volatile(
        "mma.sync.aligned.m16n8k16.row.col.f32.f16.f16.f32 "
        "{%0,%1,%2,%3}, {%4,%5,%6,%7}, {%8,%9}, {%0,%1,%2,%3};"
        : "+f"(c[0]), "+f"(c[1]), "+f"(c[2]), "+f"(c[3])
        : "r"(a0), "r"(a1), "r"(a2), "r"(a3), "r"(b0), "r"(b1));
}
// gate = 1 + tanh(silu(g)/0.6); silu via sigmoid(g) = 0.5*(1+tanh(g/2))
__device__ __forceinline__ float gatef(float g) {
    float t = tanh_fast(g * 0.5f);
    float sg = g * (1.0f + t) * (0.5f / 0.6f);
    return 1.0f + tanh_fast(sg);
}

// ================= kernel 1: zero ref accumulators (small) =================
__global__ void k_zacc(int n_acc4) {
    float4* acc4 = (float4*)g_ref_accum;
    int i = blockIdx.x * blockDim.x + threadIdx.x;
    if (i < n_acc4) acc4[i] = make_float4(0.f, 0.f, 0.f, 0.f);
}

// ================= kernel 2: segment-sum of edge_udiff over i =================
__global__ void k_refaccum(const float* __restrict__ ud,
                           const int* __restrict__ eidx, int E) {
    int e = blockIdx.x * blockDim.x + threadIdx.x;
    if (e >= E) return;
    int i = eidx[E + e];
    red4(&g_ref_accum[i * 4], ud[e * 3 + 0], ud[e * 3 + 1], ud[e * 3 + 2], 1.0f);
}

// ================= spherical-harmonic invariants (streamed) =================
__device__ __forceinline__ void sh_invariants(
    float xe, float ye, float ze, float xr, float yr, float zr, float* inv) {
    float nne = rsqrtf(xe * xe + ye * ye + ze * ze + 1e-12f);
    xe *= nne; ye *= nne; ze *= nne;
    float nnr = rsqrtf(xr * xr + yr * yr + zr * zr + 1e-12f);
    xr *= nnr; yr *= nnr; zr *= nnr;
    float st2e = xe * xe + ye * ye;
    float st2r = xr * xr + yr * yr;
    float ste = sqrtf(st2e), str = sqrtf(st2r);
    float c1e = (st2e > 0.0f) ? xe / ste : 0.0f;
    float s1e = (st2e > 0.0f) ? ye / ste : 0.0f;
    float c1r = (st2r > 0.0f) ? xr / str : 0.0f;
    float s1r = (st2r > 0.0f) ? yr / str : 0.0f;

    float acc[7];
#pragma unroll
    for (int l = 0; l < 7; l++) acc[l] = 0.0f;

    float de = 0.28209479177387814f, dr = 0.28209479177387814f;
    float ce = 1.0f, se = 0.0f, cr = 1.0f, sr = 0.0f;
#pragma unroll
    for (int m = 0; m <= 6; m++) {
        if (m > 0) {
            float km = sqrtf((2.0f * m + 1.0f) / (2.0f * m));
            de = -km * ste * de;
            dr = -km * str * dr;
            float ce2 = c1e * ce - s1e * se; se = s1e * ce + c1e * se; ce = ce2;
            float cr2 = c1r * cr - s1r * sr; sr = s1r * cr + c1r * sr; cr = cr2;
        }
        float w = (m == 0) ? 1.0f : 2.0f * (ce * cr + se * sr);
        float pe1 = de, pr1 = dr;
        acc[m] += w * pe1 * pr1;
        if (m < 6) {
            float kp = sqrtf(2.0f * m + 3.0f);
            float pe = kp * ze * de;
            float pr = kp * zr * dr;
            acc[m + 1] += w * pe * pr;
            float pe0 = pe1, pr0 = pr1;
#pragma unroll
            for (int l = m + 2; l <= 6; l++) {
                float fl = (float)l;
                float a = sqrtf((4.0f * fl * fl - 1.0f) / (fl * fl - (float)(m * m)));
                float b = sqrtf(((fl - 1.0f) * (fl - 1.0f) - (float)(m * m)) /
                                (4.0f * (fl - 1.0f) * (fl - 1.0f) - 1.0f));
                float pen = a * (ze * pe - b * pe0); pe0 = pe; pe = pen;
                float prn = a * (zr * pr - b * pr0); pr0 = pr; pr = prn;
                acc[l] += w * pe * pr;
            }
        }
    }
    const float fourpi = 12.566370614359172f;
#pragma unroll
    for (int l = 0; l < 7; l++) inv[l] = acc[l] * (fourpi / (2.0f * l + 1.0f));
}

// ====== kernel 3: fused pre-work — roles by block range (all independent) ======
#define GB 1563
#define SB 888
#define ZB 400

__global__ void __launch_bounds__(256)
k_pre(const float* __restrict__ ud, const int* __restrict__ eidx,
      const float* __restrict__ ln_g, const float* __restrict__ ln_b,
      const float* __restrict__ ns, const float* __restrict__ W1,
      const float* __restrict__ b1, const float* __restrict__ W2,
      const float* __restrict__ b2,
      float4* __restrict__ out4, int n_out4, int N, int E) {
    __shared__ float sW1[64 * 32];
    __shared__ float sW2[32 * 192];
    int tid = threadIdx.x;
    int bid = blockIdx.x;

    if (bid < GB) {
        // ---------------- geom role (ref-vec normalize folded in) ----------
        int e = bid * 256 + tid;
        if (e >= E) return;
        float ux = ud[e * 3 + 0], uy = ud[e * 3 + 1], uz = ud[e * 3 + 2];
        int i = __ldg(&eidx[E + e]);
        float4 a = *(const float4*)&g_ref_accum[i * 4];
        float ic = 1.0f / fmaxf(a.w, 1.0f);
        float rx = a.x * ic, ry = a.y * ic, rz = a.z * ic;
        float norm = sqrtf(rx * rx + ry * ry + rz * rz + 1e-9f);
        float inm = 1.0f / norm;
        rx *= inm; ry *= inm; rz *= inm;
        if (norm < 5e-5f) { rx = 1.0f; ry = 0.0f; rz = 0.0f; }

        float inv[7];
        sh_invariants(ux, uy, uz, rx, ry, rz, inv);
        float mu = 0.0f;
#pragma unroll
        for (int l = 0; l < 7; l++) mu += inv[l];
        mu *= (1.0f / 7.0f);
        float var = 0.0f;
#pragma unroll
        for (int l = 0; l < 7; l++) { float d = inv[l] - mu; var += d * d; }
        var *= (1.0f / 7.0f);
        float isd = rsqrtf(var + 1e-5f);
        float o[8];
        o[0] = ux * rx + uy * ry + uz * rz;
#pragma unroll
        for (int l = 0; l < 7; l++)
            o[1 + l] = (inv[l] - mu) * isd * ln_g[l] + ln_b[l];
        float4* gg = (float4*)(g_geom + (size_t)e * 8);
        gg[0] = make_float4(o[0], o[1], o[2], o[3]);
        gg[1] = make_float4(o[4], o[5], o[6], o[7]);
        return;
    }
    if (bid >= GB + SB) {
        // ---------------- zero-out role ----------------
        int zb = bid - GB - SB;
        float4 z = make_float4(0.f, 0.f, 0.f, 0.f);
        for (int i = zb * 256 + tid; i < n_out4; i += ZB * 256) out4[i] = z;
        return;
    }

    // ---------------- sproj role (fp16 output) ----------------
    int sbid = bid - GB;
    for (int q = tid; q < 64 * 32; q += 256) sW1[q] = W1[q];
    for (int q = tid; q < 32 * 192; q += 256) sW2[q] = W2[q];
    __syncthreads();
    const u64* sW2u = (const u64*)sW2;
    const float2* b2p = (const float2*)b2;
    int lane = tid & 31, warp = tid >> 5;

    u64 bb[3];
#pragma unroll
    for (int k = 0; k < 3; k++) {
        float2 t = b2p[lane + 32 * k];
        bb[k] = pk2(t.x, t.y);
    }
    float b1v = b1[lane];

    int npairs = (N + 1) >> 1;
    for (int p = sbid * 8 + warp; p < npairs; p += SB * 8) {
        int nA = p * 2;
        int nB = min(nA + 1, N - 1);
        float aA0 = ns[(size_t)nA * 64 + lane], aA1 = ns[(size_t)nA * 64 + 32 + lane];
        float aB0 = ns[(size_t)nB * 64 + lane], aB1 = ns[(size_t)nB * 64 + 32 + lane];
        float tA = b1v, tB = b1v;
#pragma unroll
        for (int r = 0; r < 64; r++) {
            float w = sW1[r * 32 + lane];
            float vA = __shfl_sync(0xffffffffu, (r < 32) ? aA0 : aA1, r & 31);
            float vB = __shfl_sync(0xffffffffu, (r < 32) ? aB0 : aB1, r & 31);
            tA = fmaf(vA, w, tA);
            tB = fmaf(vB, w, tB);
        }
        tA = __fdividef(tA, 1.0f + __expf(-tA)) * (1.0f / 0.6f);
        tB = __fdividef(tB, 1.0f + __expf(-tB)) * (1.0f / 0.6f);
        u64 oA[3], oB[3];
#pragma unroll
        for (int k = 0; k < 3; k++) { oA[k] = bb[k]; oB[k] = bb[k]; }
#pragma unroll
        for (int r = 0; r < 32; r++) {
            u64 w0 = sW2u[r * 96 + lane];
            u64 w1 = sW2u[r * 96 + 32 + lane];
            u64 w2 = sW2u[r * 96 + 64 + lane];
            float vA = __shfl_sync(0xffffffffu, tA, r);
            float vB = __shfl_sync(0xffffffffu, tB, r);
            u64 vvA = pk2(vA, vA), vvB = pk2(vB, vB);
            oA[0] = ffma2(vvA, w0, oA[0]);
            oA[1] = ffma2(vvA, w1, oA[1]);
            oA[2] = ffma2(vvA, w2, oA[2]);
            oB[0] = ffma2(vvB, w0, oB[0]);
            oB[1] = ffma2(vvB, w1, oB[1]);
            oB[2] = ffma2(vvB, w2, oB[2]);
        }
        __half2* outA = g_sproj_h + (size_t)nA * 96;
#pragma unroll
        for (int k = 0; k < 3; k++) {
            float lo, hi; upk2(oA[k], lo, hi);
            outA[lane + 32 * k] = __floats2half2_rn(lo, hi);
        }
        if (nB != nA) {
            __half2* outB = g_sproj_h + (size_t)nB * 96;
#pragma unroll
            for (int k = 0; k < 3; k++) {
                float lo, hi; upk2(oB[k], lo, hi);
                outB[lane + 32 * k] = __floats2half2_rn(lo, hi);
            }
        }
    }
}

// ================= kernel 4: fp16 MMA GEMM + fused gate epilogue =================
// Persistent CTAs, 256 threads = 8 warps (4 m-warps x 2 n-warps).
// Tile: 64 edges x 192 cols, K = 64 (4 chunks of k16). Warp: 16 x 96.
#define HS 72   // half stride per row (A and B smem)

__global__ void __launch_bounds__(256, 2)
k_gemm(const float* __restrict__ rbf, const int* __restrict__ eidx,
       const float* __restrict__ W_edge, const float* __restrict__ b_edge,
       const float* __restrict__ W_inv, const float* __restrict__ b_inv,
       int E) {
    extern __shared__ float sm[];
    __half* sBh = (__half*)sm;            // 192*HS halves (n-major, k contig)
    __half* sAh = sBh + 192 * HS;         // 64*HS halves (row-major)
    float* sG  = (float*)(sAh + 64 * HS); // 64*8 geom
    float* sWi = sG + 512;                // 8*192 W_inv
    float* sBe = sWi + 1536;              // 192
    float* sBi = sBe + 192;               // 192
    int*   sJ  = (int*)(sBi + 192);       // 64

    int tid = threadIdx.x;
    int lane = tid & 31, warp = tid >> 5;
    int wm = warp >> 1, wn = warp & 1;
    int gid = lane >> 2, tig = lane & 3;

    // persistent staging: B=W_edge^T (fp16), W_inv, biases
    for (int i = tid; i < 64 * 192; i += 256) {
        int k = i / 192, n = i - k * 192;
        sBh[n * HS + k] = __float2half_rn(W_edge[i]);
    }
    for (int i = tid; i < 8 * 192; i += 256) sWi[i] = W_inv[i];
    if (tid < 192) { sBe[tid] = b_edge[tid]; sBi[tid] = b_inv[tid]; }

    const u64* sWi64 = (const u64*)sWi;
    const float2* sBe2 = (const float2*)sBe;
    const float2* sBi2 = (const float2*)sBi;

    int r0 = wm * 16 + gid;
    int nb_base = wn * 96;
    const float inv_sqrt3 = 0.57735026918962576f;

    int ntiles = (E + GTE - 1) / GTE;
    for (int t = blockIdx.x; t < ntiles; t += gridDim.x) {
        int e0 = t * GTE;
        __syncthreads();  // staging buffers free (also covers first-iter staging)

        // stage A tile (f32 -> fp16), 8 halves per iteration
        for (int i = tid; i < 64 * 8; i += 256) {
            int r = i >> 3, c8 = i & 7;
            int e = min(e0 + r, E - 1);
            const float4* src = (const float4*)(rbf + (size_t)e * 64 + c8 * 8);
            float4 v0 = __ldg(src);
            float4 v1 = __ldg(src + 1);
            uint4 u;
            u.x = f2h2(v0.x, v0.y);
            u.y = f2h2(v0.z, v0.w);
            u.z = f2h2(v1.x, v1.y);
            u.w = f2h2(v1.z, v1.w);
            *(uint4*)(sAh + r * HS + c8 * 8) = u;
        }
        // stage geom + j-index
        if (tid < 128) {
            int e = min(e0 + (tid >> 1), E - 1);
            ((float4*)sG)[tid] =
                __ldg((const float4*)(g_geom + (size_t)e * 8) + (tid & 1));
        }
        if (tid < 64) sJ[tid] = __ldg(&eidx[min(e0 + tid, E - 1)]);
        __syncthreads();

        // ---- MMA mainloop: 4 k16-chunks ----
        float acc[12][4];
#pragma unroll
        for (int nb = 0; nb < 12; nb++)
            acc[nb][0] = acc[nb][1] = acc[nb][2] = acc[nb][3] = 0.0f;
#pragma unroll
        for (int kc = 0; kc < 4; kc++) {
            int kb = kc * 16 + tig * 2;
            uint32_t a0 = *(const uint32_t*)(sAh + r0 * HS + kb);
            uint32_t a1 = *(const uint32_t*)(sAh + (r0 + 8) * HS + kb);
            uint32_t a2 = *(const uint32_t*)(sAh + r0 * HS + kb + 8);
            uint32_t a3 = *(const uint32_t*)(sAh + (r0 + 8) * HS + kb + 8);
#pragma unroll
            for (int nb = 0; nb < 12; nb++) {
                int n = nb_base + nb * 8 + gid;
                uint32_t b0 = *(const uint32_t*)(sBh + n * HS + kb);
                uint32_t b1 = *(const uint32_t*)(sBh + n * HS + kb + 8);
                mma_f16(acc[nb], a0, a1, a2, a3, b0, b1);
            }
        }

        // ---- fused epilogue: gate + bias + sproj, per (edge,col) element ----
        u64 gr0[8], gr1[8];
#pragma unroll
        for (int q = 0; q < 8; q++) {
            float v0 = sG[r0 * 8 + q], v1 = sG[(r0 + 8) * 8 + q];
            gr0[q] = pk2(v0, v0);
            gr1[q] = pk2(v1, v1);
        }
        int j0 = sJ[r0], j1 = sJ[r0 + 8];
        bool val0 = (e0 + r0) < E, val1 = (e0 + r0 + 8) < E;
        __half* xrow0 = g_x + (size_t)(e0 + r0) * 192;
        __half* xrow1 = g_x + (size_t)(e0 + r0 + 8) * 192;
#pragma unroll
        for (int nb = 0; nb < 12; nb++) {
            int col = nb_base + nb * 8 + tig * 2;
            int ch = col >> 1;
            u64 g0 = 0ull, g1 = 0ull;
#pragma unroll
            for (int q = 0; q < 8; q++) {
                u64 w = sWi64[q * 96 + ch];
                g0 = ffma2(gr0[q], w, g0);
                g1 = ffma2(gr1[q], w, g1);
            }
            float2 bi = sBi2[ch];
            float2 be = sBe2[ch];
            float g00, g01, g10, g11;
            upk2(g0, g00, g01);
            upk2(g1, g10, g11);
            float f00 = gatef(g00 + bi.x), f01 = gatef(g01 + bi.y);
            float f10 = gatef(g10 + bi.x), f11 = gatef(g11 + bi.y);
            float2 sp0 = __half22float2(__ldg(&g_sproj_h[(size_t)j0 * 96 + ch]));
            float2 sp1 = __half22float2(__ldg(&g_sproj_h[(size_t)j1 * 96 + ch]));
            float x00 = sp0.x * (acc[nb][0] + be.x) * f00 * inv_sqrt3;
            float x01 = sp0.y * (acc[nb][1] + be.y) * f01 * inv_sqrt3;
            float x10 = sp1.x * (acc[nb][2] + be.x) * f10 * inv_sqrt3;
            float x11 = sp1.y * (acc[nb][3] + be.y) * f11 * inv_sqrt3;
            if (val0) *(__half2*)(xrow0 + col) = __floats2half2_rn(x00, x01);
            if (val1) *(__half2*)(xrow1 + col) = __floats2half2_rn(x10, x11);
        }
    }
}

// ================= kernel 5: scatter (warp per edge) =================
__global__ void __launch_bounds__(256)
k_scatter(const float* __restrict__ ud, const int* __restrict__ eidx,
          const float* __restrict__ nv, float* __restrict__ out, int N, int E) {
    __shared__ __align__(16) float sX[8][192];
    int lane = threadIdx.x & 31, warp = threadIdx.x >> 5;
    float* xf = sX[warp];
    float* outv = out + (size_t)N * 64;
    const float ish = 0.125f;

    for (int e = blockIdx.x * 8 + warp; e < E; e += gridDim.x * 8) {
        const __half2* xr = (const __half2*)(g_x + (size_t)e * 192);
        float2 v0 = __half22float2(__ldg(xr + lane));        // x1
        float2 v1 = __half22float2(__ldg(xr + 32 + lane));   // x2
        float2 v2 = __half22float2(__ldg(xr + 64 + lane));   // x3
        ((float2*)xf)[lane] = v0;
        ((float2*)xf)[32 + lane] = v1;
        ((float2*)xf)[64 + lane] = v2;
        int j = __ldg(&eidx[e]), in = __ldg(&eidx[E + e]);
        float ud0 = __ldg(&ud[e * 3 + 0]);
        float ud1 = __ldg(&ud[e * 3 + 1]);
        float ud2 = __ldg(&ud[e * 3 + 2]);
        __syncwarp();

        if (lane < 16) {  // delta_scalar: x3
            const float4 x3v = *(const float4*)&xf[128 + 4 * lane];
            red4(&out[(size_t)in * 64 + 4 * lane], x3v.x, x3v.y, x3v.z, x3v.w);
        }
        {  // delta_vector d=0,1: o = 4*lane in [0,128)
            int o = 4 * lane;
            float udd = (o >> 6) ? ud1 : ud0;
            int h = o & 63;
            const float4 f1 = *(const float4*)&xf[h];
            const float4 f2 = *(const float4*)&xf[64 + h];
            float4 nvv = __ldg((const float4*)(nv + (size_t)j * 192 + o));
            red4(&outv[(size_t)in * 192 + o],
                 (f1.x * nvv.x + f2.x * udd) * ish,
                 (f1.y * nvv.y + f2.y * udd) * ish,
                 (f1.z * nvv.z + f2.z * udd) * ish,
                 (f1.w * nvv.w + f2.w * udd) * ish);
        }
        if (lane < 16) {  // delta_vector d=2
            int o = 128 + 4 * lane;
            int h = 4 * lane;
            const float4 f1 = *(const float4*)&xf[h];
            const float4 f2 = *(const float4*)&xf[64 + h];
            float4 nvv = __ldg((const float4*)(nv + (size_t)j * 192 + o));
            red4(&outv[(size_t)in * 192 + o],
                 (f1.x * nvv.x + f2.x * ud2) * ish,
                 (f1.y * nvv.y + f2.y * ud2) * ish,
                 (f1.z * nvv.z + f2.z * ud2) * ish,
                 (f1.w * nvv.w + f2.w * ud2) * ish);
        }
        __syncwarp();
    }
}

// ================= launch =================
extern "C" void kernel_launch(void* const* d_in, const int* in_sizes, int n_in,
                              void* d_out, int out_size) {
    const float* node_scalar = (const float*)d_in[0];
    const float* node_vector = (const float*)d_in[1];
    const float* edge_rbf    = (const float*)d_in[2];
    const float* edge_udiff  = (const float*)d_in[3];
    const int*   edge_index  = (const int*)d_in[4];
    const float* W_edge      = (const float*)d_in[5];
    const float* b_edge      = (const float*)d_in[6];
    const float* W_x1        = (const float*)d_in[7];
    const float* b_x1        = (const float*)d_in[8];
    const float* W_x2        = (const float*)d_in[9];
    const float* b_x2        = (const float*)d_in[10];
    const float* ln_g        = (const float*)d_in[11];
    const float* ln_b        = (const float*)d_in[12];
    const float* W_inv       = (const float*)d_in[13];
    const float* b_inv       = (const float*)d_in[14];

    int N = in_sizes[0] / 64;
    int E = in_sizes[3] / 3;
    float* out = (float*)d_out;

    // dynamic smem for k_gemm: Bh + Ah (halves) + geom + W_inv + biases + J
    int smem_gemm = (192 * HS + 64 * HS) * 2 + (512 + 1536 + 192 + 192) * 4 + 64 * 4;
    cudaFuncSetAttribute(k_gemm, cudaFuncAttributeMaxDynamicSharedMemorySize,
                         smem_gemm);

    k_zacc<<<(N + 255) / 256, 256>>>(N);  // N float4 accumulators
    k_refaccum<<<(E + 255) / 256, 256>>>(edge_udiff, edge_index, E);
    // fused independent pre-work: geom (incl. refvec) + sproj + zero-out
    k_pre<<<GB + SB + ZB, 256>>>(edge_udiff, edge_index, ln_g, ln_b,
                                 node_scalar, W_x1, b_x1, W_x2, b_x2,
                                 (float4*)out, out_size / 4, N, E);
    k_gemm<<<296, 256, smem_gemm>>>(edge_rbf, edge_index, W_edge, b_edge,
                                    W_inv, b_inv, E);
    k_scatter<<<2960, 256>>>(edge_udiff, edge_index, node_vector, out, N, E);
}

// round 13
// speedup vs baseline: 1.7782x; 1.0894x over previous
#include <cuda_runtime.h>
#include <cuda_fp16.h>
#include <math.h>
#include <stdint.h>

#define NMAX 50000
#define EMAX 400000
#define GTE 64   // edges per gemm tile

// ---- scratch (device globals; no allocation allowed) ----
__device__ float g_ref_accum[NMAX * 4];   // sum x,y,z + count
__device__ __half2 g_sproj_h[(size_t)NMAX * 96];  // fp16 node projections
__device__ float g_geom[(size_t)EMAX * 8];
__device__ __half g_x[(size_t)EMAX * 192];  // gated per-edge messages (fp16)

// ---------------- helpers ----------------
typedef unsigned long long u64;
__device__ __forceinline__ u64 pk2(float lo, float hi) {
    u64 r;
    asm("mov.b64 %0, {%1, %2};" : "=l"(r) : "f"(lo), "f"(hi));
    return r;
}
__device__ __forceinline__ void upk2(u64 v, float& lo, float& hi) {
    asm("mov.b64 {%0, %1}, %2;" : "=f"(lo), "=f"(hi) : "l"(v));
}
__device__ __forceinline__ u64 ffma2(u64 a, u64 b, u64 c) {
    u64 d;
    asm("fma.rn.f32x2 %0, %1, %2, %3;" : "=l"(d) : "l"(a), "l"(b), "l"(c));
    return d;
}
__device__ __forceinline__ float tanh_fast(float x) {
    float y;
    asm("tanh.approx.f32 %0, %1;" : "=f"(y) : "f"(x));
    return y;
}
__device__ __forceinline__ void red4(float* a, float x, float y, float z, float w) {
    asm volatile("red.global.add.v4.f32 [%0], {%1, %2, %3, %4};"
                 :: "l"(a), "f"(x), "f"(y), "f"(z), "f"(w) : "memory");
}
__device__ __forceinline__ uint32_t f2h2(float a, float b) {
    __half2 h = __floats2half2_rn(a, b);
    return *(uint32_t*)&h;
}
__device__ __forceinline__ void mma_f16(float c[4], uint32_t a0, uint32_t a1,
                                        uint32_t a2, uint32_t a3,
                                        uint32_t b0, uint32_t b1) {
    asm volatile(
        "mma.sync.aligned.m16n8k16.row.col.f32.f16.f16.f32 "
        "{%0,%1,%2,%3}, {%4,%5,%6,%7}, {%8,%9}, {%0,%1,%2,%3};"
        : "+f"(c[0]), "+f"(c[1]), "+f"(c[2]), "+f"(c[3])
        : "r"(a0), "r"(a1), "r"(a2), "r"(a3), "r"(b0), "r"(b1));
}
__device__ __forceinline__ void mma_f16_k8(float c[4], uint32_t a0, uint32_t a1,
                                           uint32_t b0) {
    asm volatile(
        "mma.sync.aligned.m16n8k8.row.col.f32.f16.f16.f32 "
        "{%0,%1,%2,%3}, {%4,%5}, {%6}, {%0,%1,%2,%3};"
        : "+f"(c[0]), "+f"(c[1]), "+f"(c[2]), "+f"(c[3])
        : "r"(a0), "r"(a1), "r"(b0));
}
// gate = 1 + tanh(silu(g)/0.6); silu via sigmoid(g) = 0.5*(1+tanh(g/2))
__device__ __forceinline__ float gatef(float g) {
    float t = tanh_fast(g * 0.5f);
    float sg = g * (1.0f + t) * (0.5f / 0.6f);
    return 1.0f + tanh_fast(sg);
}

// ================= kernel 1: zero ref accumulators (small) =================
__global__ void k_zacc(int n_acc4) {
    float4* acc4 = (float4*)g_ref_accum;
    int i = blockIdx.x * blockDim.x + threadIdx.x;
    if (i < n_acc4) acc4[i] = make_float4(0.f, 0.f, 0.f, 0.f);
}

// ================= kernel 2: segment-sum of edge_udiff over i =================
__global__ void k_refaccum(const float* __restrict__ ud,
                           const int* __restrict__ eidx, int E) {
    int e = blockIdx.x * blockDim.x + threadIdx.x;
    if (e >= E) return;
    int i = eidx[E + e];
    red4(&g_ref_accum[i * 4], ud[e * 3 + 0], ud[e * 3 + 1], ud[e * 3 + 2], 1.0f);
}

// ================= spherical-harmonic invariants (streamed) =================
__device__ __forceinline__ void sh_invariants(
    float xe, float ye, float ze, float xr, float yr, float zr, float* inv) {
    float nne = rsqrtf(xe * xe + ye * ye + ze * ze + 1e-12f);
    xe *= nne; ye *= nne; ze *= nne;
    float nnr = rsqrtf(xr * xr + yr * yr + zr * zr + 1e-12f);
    xr *= nnr; yr *= nnr; zr *= nnr;
    float st2e = xe * xe + ye * ye;
    float st2r = xr * xr + yr * yr;
    float ste = sqrtf(st2e), str = sqrtf(st2r);
    float c1e = (st2e > 0.0f) ? xe / ste : 0.0f;
    float s1e = (st2e > 0.0f) ? ye / ste : 0.0f;
    float c1r = (st2r > 0.0f) ? xr / str : 0.0f;
    float s1r = (st2r > 0.0f) ? yr / str : 0.0f;

    float acc[7];
#pragma unroll
    for (int l = 0; l < 7; l++) acc[l] = 0.0f;

    float de = 0.28209479177387814f, dr = 0.28209479177387814f;
    float ce = 1.0f, se = 0.0f, cr = 1.0f, sr = 0.0f;
#pragma unroll
    for (int m = 0; m <= 6; m++) {
        if (m > 0) {
            float km = sqrtf((2.0f * m + 1.0f) / (2.0f * m));
            de = -km * ste * de;
            dr = -km * str * dr;
            float ce2 = c1e * ce - s1e * se; se = s1e * ce + c1e * se; ce = ce2;
            float cr2 = c1r * cr - s1r * sr; sr = s1r * cr + c1r * sr; cr = cr2;
        }
        float w = (m == 0) ? 1.0f : 2.0f * (ce * cr + se * sr);
        float pe1 = de, pr1 = dr;
        acc[m] += w * pe1 * pr1;
        if (m < 6) {
            float kp = sqrtf(2.0f * m + 3.0f);
            float pe = kp * ze * de;
            float pr = kp * zr * dr;
            acc[m + 1] += w * pe * pr;
            float pe0 = pe1, pr0 = pr1;
#pragma unroll
            for (int l = m + 2; l <= 6; l++) {
                float fl = (float)l;
                float a = sqrtf((4.0f * fl * fl - 1.0f) / (fl * fl - (float)(m * m)));
                float b = sqrtf(((fl - 1.0f) * (fl - 1.0f) - (float)(m * m)) /
                                (4.0f * (fl - 1.0f) * (fl - 1.0f) - 1.0f));
                float pen = a * (ze * pe - b * pe0); pe0 = pe; pe = pen;
                float prn = a * (zr * pr - b * pr0); pr0 = pr; pr = prn;
                acc[l] += w * pe * pr;
            }
        }
    }
    const float fourpi = 12.566370614359172f;
#pragma unroll
    for (int l = 0; l < 7; l++) inv[l] = acc[l] * (fourpi / (2.0f * l + 1.0f));
}

// ====== kernel 3: fused pre-work — roles by block range (all independent) ======
#define GB 1563
#define SB 888
#define ZB 400

__global__ void __launch_bounds__(256)
k_pre(const float* __restrict__ ud, const int* __restrict__ eidx,
      const float* __restrict__ ln_g, const float* __restrict__ ln_b,
      const float* __restrict__ ns, const float* __restrict__ W1,
      const float* __restrict__ b1, const float* __restrict__ W2,
      const float* __restrict__ b2,
      float4* __restrict__ out4, int n_out4, int N, int E) {
    __shared__ float sW1[64 * 32];
    __shared__ float sW2[32 * 192];
    int tid = threadIdx.x;
    int bid = blockIdx.x;

    if (bid < GB) {
        // ---------------- geom role (ref-vec normalize folded in) ----------
        int e = bid * 256 + tid;
        if (e >= E) return;
        float ux = ud[e * 3 + 0], uy = ud[e * 3 + 1], uz = ud[e * 3 + 2];
        int i = __ldg(&eidx[E + e]);
        float4 a = *(const float4*)&g_ref_accum[i * 4];
        float ic = 1.0f / fmaxf(a.w, 1.0f);
        float rx = a.x * ic, ry = a.y * ic, rz = a.z * ic;
        float norm = sqrtf(rx * rx + ry * ry + rz * rz + 1e-9f);
        float inm = 1.0f / norm;
        rx *= inm; ry *= inm; rz *= inm;
        if (norm < 5e-5f) { rx = 1.0f; ry = 0.0f; rz = 0.0f; }

        float inv[7];
        sh_invariants(ux, uy, uz, rx, ry, rz, inv);
        float mu = 0.0f;
#pragma unroll
        for (int l = 0; l < 7; l++) mu += inv[l];
        mu *= (1.0f / 7.0f);
        float var = 0.0f;
#pragma unroll
        for (int l = 0; l < 7; l++) { float d = inv[l] - mu; var += d * d; }
        var *= (1.0f / 7.0f);
        float isd = rsqrtf(var + 1e-5f);
        float o[8];
        o[0] = ux * rx + uy * ry + uz * rz;
#pragma unroll
        for (int l = 0; l < 7; l++)
            o[1 + l] = (inv[l] - mu) * isd * ln_g[l] + ln_b[l];
        float4* gg = (float4*)(g_geom + (size_t)e * 8);
        gg[0] = make_float4(o[0], o[1], o[2], o[3]);
        gg[1] = make_float4(o[4], o[5], o[6], o[7]);
        return;
    }
    if (bid >= GB + SB) {
        // ---------------- zero-out role ----------------
        int zb = bid - GB - SB;
        float4 z = make_float4(0.f, 0.f, 0.f, 0.f);
        for (int i = zb * 256 + tid; i < n_out4; i += ZB * 256) out4[i] = z;
        return;
    }

    // ---------------- sproj role (fp16 output) ----------------
    int sbid = bid - GB;
    for (int q = tid; q < 64 * 32; q += 256) sW1[q] = W1[q];
    for (int q = tid; q < 32 * 192; q += 256) sW2[q] = W2[q];
    __syncthreads();
    const u64* sW2u = (const u64*)sW2;
    const float2* b2p = (const float2*)b2;
    int lane = tid & 31, warp = tid >> 5;

    u64 bb[3];
#pragma unroll
    for (int k = 0; k < 3; k++) {
        float2 t = b2p[lane + 32 * k];
        bb[k] = pk2(t.x, t.y);
    }
    float b1v = b1[lane];

    int npairs = (N + 1) >> 1;
    for (int p = sbid * 8 + warp; p < npairs; p += SB * 8) {
        int nA = p * 2;
        int nB = min(nA + 1, N - 1);
        float aA0 = ns[(size_t)nA * 64 + lane], aA1 = ns[(size_t)nA * 64 + 32 + lane];
        float aB0 = ns[(size_t)nB * 64 + lane], aB1 = ns[(size_t)nB * 64 + 32 + lane];
        float tA = b1v, tB = b1v;
#pragma unroll
        for (int r = 0; r < 64; r++) {
            float w = sW1[r * 32 + lane];
            float vA = __shfl_sync(0xffffffffu, (r < 32) ? aA0 : aA1, r & 31);
            float vB = __shfl_sync(0xffffffffu, (r < 32) ? aB0 : aB1, r & 31);
            tA = fmaf(vA, w, tA);
            tB = fmaf(vB, w, tB);
        }
        tA = __fdividef(tA, 1.0f + __expf(-tA)) * (1.0f / 0.6f);
        tB = __fdividef(tB, 1.0f + __expf(-tB)) * (1.0f / 0.6f);
        u64 oA[3], oB[3];
#pragma unroll
        for (int k = 0; k < 3; k++) { oA[k] = bb[k]; oB[k] = bb[k]; }
#pragma unroll
        for (int r = 0; r < 32; r++) {
            u64 w0 = sW2u[r * 96 + lane];
            u64 w1 = sW2u[r * 96 + 32 + lane];
            u64 w2 = sW2u[r * 96 + 64 + lane];
            float vA = __shfl_sync(0xffffffffu, tA, r);
            float vB = __shfl_sync(0xffffffffu, tB, r);
            u64 vvA = pk2(vA, vA), vvB = pk2(vB, vB);
            oA[0] = ffma2(vvA, w0, oA[0]);
            oA[1] = ffma2(vvA, w1, oA[1]);
            oA[2] = ffma2(vvA, w2, oA[2]);
            oB[0] = ffma2(vvB, w0, oB[0]);
            oB[1] = ffma2(vvB, w1, oB[1]);
            oB[2] = ffma2(vvB, w2, oB[2]);
        }
        __half2* outA = g_sproj_h + (size_t)nA * 96;
#pragma unroll
        for (int k = 0; k < 3; k++) {
            float lo, hi; upk2(oA[k], lo, hi);
            outA[lane + 32 * k] = __floats2half2_rn(lo, hi);
        }
        if (nB != nA) {
            __half2* outB = g_sproj_h + (size_t)nB * 96;
#pragma unroll
            for (int k = 0; k < 3; k++) {
                float lo, hi; upk2(oB[k], lo, hi);
                outB[lane + 32 * k] = __floats2half2_rn(lo, hi);
            }
        }
    }
}

// ====== kernel 4: fp16 MMA GEMM + tensor-core gate + fused epilogue ======
// Persistent CTAs, 256 threads = 8 warps (4 m-warps x 2 n-warps).
// Tile: 64 edges x 192 cols, K = 64 (4 chunks of k16). Warp: 16 x 96,
// processed as 2 halves of 6 n-blocks (gate MMA k8, then main MMA k16).
#define HS 72   // half stride per row (A and B smem)

__global__ void __launch_bounds__(256, 2)
k_gemm(const float* __restrict__ rbf, const int* __restrict__ eidx,
       const float* __restrict__ W_edge, const float* __restrict__ b_edge,
       const float* __restrict__ W_inv, const float* __restrict__ b_inv,
       int E) {
    extern __shared__ float sm[];
    __half* sBh  = (__half*)sm;             // 192*HS (W_edge^T, k contig)
    __half* sAh  = sBh + 192 * HS;          // 64*HS  (rbf tile)
    __half* sWih = sAh + 64 * HS;           // 192*8  (W_inv, n-major k contig)
    __half* sGh  = sWih + 192 * 8;          // 64*8   (geom tile)
    float* sBe = (float*)(sGh + 64 * 8);    // 192
    float* sBi = sBe + 192;                 // 192
    int*   sJ  = (int*)(sBi + 192);         // 64

    int tid = threadIdx.x;
    int lane = tid & 31, warp = tid >> 5;
    int wm = warp >> 1, wn = warp & 1;
    int gid = lane >> 2, tig = lane & 3;

    // persistent staging: W_edge^T (fp16), W_inv (fp16 fragment layout), biases
    for (int i = tid; i < 64 * 192; i += 256) {
        int k = i / 192, n = i - k * 192;
        sBh[n * HS + k] = __float2half_rn(W_edge[i]);
    }
    for (int i = tid; i < 8 * 192; i += 256) {
        int q = i / 192, n = i - q * 192;
        sWih[n * 8 + q] = __float2half_rn(W_inv[i]);
    }
    if (tid < 192) { sBe[tid] = b_edge[tid]; sBi[tid] = b_inv[tid]; }

    const float2* sBe2 = (const float2*)sBe;
    const float2* sBi2 = (const float2*)sBi;

    int r0 = wm * 16 + gid;
    int nb_base = wn * 96;
    const float inv_sqrt3 = 0.57735026918962576f;

    int ntiles = (E + GTE - 1) / GTE;
    for (int t = blockIdx.x; t < ntiles; t += gridDim.x) {
        int e0 = t * GTE;
        __syncthreads();  // staging buffers free (also covers first-iter staging)

        // stage A tile (f32 -> fp16)
        for (int i = tid; i < 64 * 8; i += 256) {
            int r = i >> 3, c8 = i & 7;
            int e = min(e0 + r, E - 1);
            const float4* src = (const float4*)(rbf + (size_t)e * 64 + c8 * 8);
            float4 v0 = __ldg(src);
            float4 v1 = __ldg(src + 1);
            uint4 u;
            u.x = f2h2(v0.x, v0.y);
            u.y = f2h2(v0.z, v0.w);
            u.z = f2h2(v1.x, v1.y);
            u.w = f2h2(v1.z, v1.w);
            *(uint4*)(sAh + r * HS + c8 * 8) = u;
        }
        // stage geom (fp16) + j-index
        if (tid < 64) {
            int e = min(e0 + tid, E - 1);
            const float4* gp = (const float4*)(g_geom + (size_t)e * 8);
            float4 v0 = __ldg(gp), v1 = __ldg(gp + 1);
            uint4 u;
            u.x = f2h2(v0.x, v0.y);
            u.y = f2h2(v0.z, v0.w);
            u.z = f2h2(v1.x, v1.y);
            u.w = f2h2(v1.z, v1.w);
            *(uint4*)(sGh + tid * 8) = u;
            sJ[tid] = __ldg(&eidx[e]);
        }
        __syncthreads();

        int j0 = sJ[r0], j1 = sJ[r0 + 8];
        bool val0 = (e0 + r0) < E, val1 = (e0 + r0 + 8) < E;
        __half* xrow0 = g_x + (size_t)(e0 + r0) * 192;
        __half* xrow1 = g_x + (size_t)(e0 + r0 + 8) * 192;

        uint32_t ga0 = *(const uint32_t*)(sGh + r0 * 8 + tig * 2);
        uint32_t ga1 = *(const uint32_t*)(sGh + (r0 + 8) * 8 + tig * 2);

#pragma unroll
        for (int h = 0; h < 2; h++) {
            int nbh = nb_base + h * 48;
            float acc[6][4], gate[6][4];

            // ---- gate MMA (k8): gacc = geom @ W_inv ----
#pragma unroll
            for (int nb = 0; nb < 6; nb++)
                acc[nb][0] = acc[nb][1] = acc[nb][2] = acc[nb][3] = 0.0f;
#pragma unroll
            for (int nb = 0; nb < 6; nb++) {
                int n = nbh + nb * 8 + gid;
                uint32_t b0 = *(const uint32_t*)(sWih + n * 8 + tig * 2);
                mma_f16_k8(acc[nb], ga0, ga1, b0);
            }
#pragma unroll
            for (int nb = 0; nb < 6; nb++) {
                int ch = (nbh + nb * 8 + tig * 2) >> 1;
                float2 bi = sBi2[ch];
                gate[nb][0] = gatef(acc[nb][0] + bi.x);
                gate[nb][1] = gatef(acc[nb][1] + bi.y);
                gate[nb][2] = gatef(acc[nb][2] + bi.x);
                gate[nb][3] = gatef(acc[nb][3] + bi.y);
                acc[nb][0] = acc[nb][1] = acc[nb][2] = acc[nb][3] = 0.0f;
            }

            // ---- main MMA (4 k16-chunks) ----
#pragma unroll
            for (int kc = 0; kc < 4; kc++) {
                int kb = kc * 16 + tig * 2;
                uint32_t a0 = *(const uint32_t*)(sAh + r0 * HS + kb);
                uint32_t a1 = *(const uint32_t*)(sAh + (r0 + 8) * HS + kb);
                uint32_t a2 = *(const uint32_t*)(sAh + r0 * HS + kb + 8);
                uint32_t a3 = *(const uint32_t*)(sAh + (r0 + 8) * HS + kb + 8);
#pragma unroll
                for (int nb = 0; nb < 6; nb++) {
                    int n = nbh + nb * 8 + gid;
                    uint32_t b0 = *(const uint32_t*)(sBh + n * HS + kb);
                    uint32_t b1 = *(const uint32_t*)(sBh + n * HS + kb + 8);
                    mma_f16(acc[nb], a0, a1, a2, a3, b0, b1);
                }
            }

            // ---- epilogue: bias + gate + sproj -> g_x (fp16) ----
#pragma unroll
            for (int nb = 0; nb < 6; nb++) {
                int col = nbh + nb * 8 + tig * 2;
                int ch = col >> 1;
                float2 be = sBe2[ch];
                float2 sp0 = __half22float2(__ldg(&g_sproj_h[(size_t)j0 * 96 + ch]));
                float2 sp1 = __half22float2(__ldg(&g_sproj_h[(size_t)j1 * 96 + ch]));
                float x00 = sp0.x * (acc[nb][0] + be.x) * gate[nb][0] * inv_sqrt3;
                float x01 = sp0.y * (acc[nb][1] + be.y) * gate[nb][1] * inv_sqrt3;
                float x10 = sp1.x * (acc[nb][2] + be.x) * gate[nb][2] * inv_sqrt3;
                float x11 = sp1.y * (acc[nb][3] + be.y) * gate[nb][3] * inv_sqrt3;
                if (val0) *(__half2*)(xrow0 + col) = __floats2half2_rn(x00, x01);
                if (val1) *(__half2*)(xrow1 + col) = __floats2half2_rn(x10, x11);
            }
        }
    }
}

// ================= kernel 5: scatter (warp per edge) =================
__global__ void __launch_bounds__(256)
k_scatter(const float* __restrict__ ud, const int* __restrict__ eidx,
          const float* __restrict__ nv, float* __restrict__ out, int N, int E) {
    __shared__ __align__(16) float sX[8][192];
    int lane = threadIdx.x & 31, warp = threadIdx.x >> 5;
    float* xf = sX[warp];
    float* outv = out + (size_t)N * 64;
    const float ish = 0.125f;

    for (int e = blockIdx.x * 8 + warp; e < E; e += gridDim.x * 8) {
        const __half2* xr = (const __half2*)(g_x + (size_t)e * 192);
        float2 v0 = __half22float2(__ldg(xr + lane));        // x1
        float2 v1 = __half22float2(__ldg(xr + 32 + lane));   // x2
        float2 v2 = __half22float2(__ldg(xr + 64 + lane));   // x3
        ((float2*)xf)[lane] = v0;
        ((float2*)xf)[32 + lane] = v1;
        ((float2*)xf)[64 + lane] = v2;
        int j = __ldg(&eidx[e]), in = __ldg(&eidx[E + e]);
        float ud0 = __ldg(&ud[e * 3 + 0]);
        float ud1 = __ldg(&ud[e * 3 + 1]);
        float ud2 = __ldg(&ud[e * 3 + 2]);
        __syncwarp();

        if (lane < 16) {  // delta_scalar: x3
            const float4 x3v = *(const float4*)&xf[128 + 4 * lane];
            red4(&out[(size_t)in * 64 + 4 * lane], x3v.x, x3v.y, x3v.z, x3v.w);
        }
        {  // delta_vector d=0,1: o = 4*lane in [0,128)
            int o = 4 * lane;
            float udd = (o >> 6) ? ud1 : ud0;
            int h = o & 63;
            const float4 f1 = *(const float4*)&xf[h];
            const float4 f2 = *(const float4*)&xf[64 + h];
            float4 nvv = __ldg((const float4*)(nv + (size_t)j * 192 + o));
            red4(&outv[(size_t)in * 192 + o],
                 (f1.x * nvv.x + f2.x * udd) * ish,
                 (f1.y * nvv.y + f2.y * udd) * ish,
                 (f1.z * nvv.z + f2.z * udd) * ish,
                 (f1.w * nvv.w + f2.w * udd) * ish);
        }
        if (lane < 16) {  // delta_vector d=2
            int o = 128 + 4 * lane;
            int h = 4 * lane;
            const float4 f1 = *(const float4*)&xf[h];
            const float4 f2 = *(const float4*)&xf[64 + h];
            float4 nvv = __ldg((const float4*)(nv + (size_t)j * 192 + o));
            red4(&outv[(size_t)in * 192 + o],
                 (f1.x * nvv.x + f2.x * ud2) * ish,
                 (f1.y * nvv.y + f2.y * ud2) * ish,
                 (f1.z * nvv.z + f2.z * ud2) * ish,
                 (f1.w * nvv.w + f2.w * ud2) * ish);
        }
        __syncwarp();
    }
}

// ================= launch =================
extern "C" void kernel_launch(void* const* d_in, const int* in_sizes, int n_in,
                              void* d_out, int out_size) {
    const float* node_scalar = (const float*)d_in[0];
    const float* node_vector = (const float*)d_in[1];
    const float* edge_rbf    = (const float*)d_in[2];
    const float* edge_udiff  = (const float*)d_in[3];
    const int*   edge_index  = (const int*)d_in[4];
    const float* W_edge      = (const float*)d_in[5];
    const float* b_edge      = (const float*)d_in[6];
    const float* W_x1        = (const float*)d_in[7];
    const float* b_x1        = (const float*)d_in[8];
    const float* W_x2        = (const float*)d_in[9];
    const float* b_x2        = (const float*)d_in[10];
    const float* ln_g        = (const float*)d_in[11];
    const float* ln_b        = (const float*)d_in[12];
    const float* W_inv       = (const float*)d_in[13];
    const float* b_inv       = (const float*)d_in[14];

    int N = in_sizes[0] / 64;
    int E = in_sizes[3] / 3;
    float* out = (float*)d_out;

    // dynamic smem for k_gemm: Bh + Ah + Wih + Gh (halves) + biases + J
    int smem_gemm = (192 * HS + 64 * HS + 192 * 8 + 64 * 8) * 2
                    + (192 + 192) * 4 + 64 * 4;
    cudaFuncSetAttribute(k_gemm, cudaFuncAttributeMaxDynamicSharedMemorySize,
                         smem_gemm);

    k_zacc<<<(N + 255) / 256, 256>>>(N);  // N float4 accumulators
    k_refaccum<<<(E + 255) / 256, 256>>>(edge_udiff, edge_index, E);
    // fused independent pre-work: geom (incl. refvec) + sproj + zero-out
    k_pre<<<GB + SB + ZB, 256>>>(edge_udiff, edge_index, ln_g, ln_b,
                                 node_scalar, W_x1, b_x1, W_x2, b_x2,
                                 (float4*)out, out_size / 4, N, E);
    k_gemm<<<296, 256, smem_gemm>>>(edge_rbf, edge_index, W_edge, b_edge,
                                    W_inv, b_inv, E);
    k_scatter<<<2960, 256>>>(edge_udiff, edge_index, node_vector, out, N, E);
}

// round 14
// speedup vs baseline: 1.8497x; 1.0402x over previous
#include <cuda_runtime.h>
#include <cuda_fp16.h>
#include <math.h>
#include <stdint.h>

#define NMAX 50000
#define EMAX 400000
#define GTE 64   // edges per gemm tile

// ---- scratch (device globals; no allocation allowed) ----
__device__ float g_ref_accum[NMAX * 4];   // sum x,y,z + count
__device__ __half2 g_sproj_h[(size_t)NMAX * 96];  // fp16 node projections
__device__ float g_geom[(size_t)EMAX * 8];
__device__ __half g_x[(size_t)EMAX * 192];  // gated per-edge messages (fp16)

// ---------------- helpers ----------------
typedef unsigned long long u64;
__device__ __forceinline__ u64 pk2(float lo, float hi) {
    u64 r;
    asm("mov.b64 %0, {%1, %2};" : "=l"(r) : "f"(lo), "f"(hi));
    return r;
}
__device__ __forceinline__ void upk2(u64 v, float& lo, float& hi) {
    asm("mov.b64 {%0, %1}, %2;" : "=f"(lo), "=f"(hi) : "l"(v));
}
__device__ __forceinline__ u64 ffma2(u64 a, u64 b, u64 c) {
    u64 d;
    asm("fma.rn.f32x2 %0, %1, %2, %3;" : "=l"(d) : "l"(a), "l"(b), "l"(c));
    return d;
}
__device__ __forceinline__ float tanh_fast(float x) {
    float y;
    asm("tanh.approx.f32 %0, %1;" : "=f"(y) : "f"(x));
    return y;
}
__device__ __forceinline__ void red4(float* a, float x, float y, float z, float w) {
    asm volatile("red.global.add.v4.f32 [%0], {%1, %2, %3, %4};"
                 :: "l"(a), "f"(x), "f"(y), "f"(z), "f"(w) : "memory");
}
__device__ __forceinline__ uint32_t f2h2(float a, float b) {
    __half2 h = __floats2half2_rn(a, b);
    return *(uint32_t*)&h;
}
__device__ __forceinline__ void mma_f16(float c[4], uint32_t a0, uint32_t a1,
                                        uint32_t a2, uint32_t a3,
                                        uint32_t b0, uint32_t b1) {
    asm volatile(
        "mma.sync.aligned.m16n8k16.row.col.f32.f16.f16.f32 "
        "{%0,%1,%2,%3}, {%4,%5,%6,%7}, {%8,%9}, {%0,%1,%2,%3};"
        : "+f"(c[0]), "+f"(c[1]), "+f"(c[2]), "+f"(c[3])
        : "r"(a0), "r"(a1), "r"(a2), "r"(a3), "r"(b0), "r"(b1));
}
__device__ __forceinline__ void mma_f16_k8(float c[4], uint32_t a0, uint32_t a1,
                                           uint32_t b0) {
    asm volatile(
        "mma.sync.aligned.m16n8k8.row.col.f32.f16.f16.f32 "
        "{%0,%1,%2,%3}, {%4,%5}, {%6}, {%0,%1,%2,%3};"
        : "+f"(c[0]), "+f"(c[1]), "+f"(c[2]), "+f"(c[3])
        : "r"(a0), "r"(a1), "r"(b0));
}
// gate = 1 + tanh(silu(g)/0.6); silu via sigmoid(g) = 0.5*(1+tanh(g/2))
__device__ __forceinline__ float gatef(float g) {
    float t = tanh_fast(g * 0.5f);
    float sg = g * (1.0f + t) * (0.5f / 0.6f);
    return 1.0f + tanh_fast(sg);
}

// ================= kernel 1: zero ref accumulators (small) =================
__global__ void k_zacc(int n_acc4) {
    float4* acc4 = (float4*)g_ref_accum;
    int i = blockIdx.x * blockDim.x + threadIdx.x;
    if (i < n_acc4) acc4[i] = make_float4(0.f, 0.f, 0.f, 0.f);
}

// ================= kernel 2: segment-sum of edge_udiff over i =================
__global__ void k_refaccum(const float* __restrict__ ud,
                           const int* __restrict__ eidx, int E) {
    int e = blockIdx.x * blockDim.x + threadIdx.x;
    if (e >= E) return;
    int i = eidx[E + e];
    red4(&g_ref_accum[i * 4], ud[e * 3 + 0], ud[e * 3 + 1], ud[e * 3 + 2], 1.0f);
}

// ================= spherical-harmonic invariants (streamed) =================
__device__ __forceinline__ void sh_invariants(
    float xe, float ye, float ze, float xr, float yr, float zr, float* inv) {
    float nne = rsqrtf(xe * xe + ye * ye + ze * ze + 1e-12f);
    xe *= nne; ye *= nne; ze *= nne;
    float nnr = rsqrtf(xr * xr + yr * yr + zr * zr + 1e-12f);
    xr *= nnr; yr *= nnr; zr *= nnr;
    float st2e = xe * xe + ye * ye;
    float st2r = xr * xr + yr * yr;
    float ste = sqrtf(st2e), str = sqrtf(st2r);
    float c1e = (st2e > 0.0f) ? xe / ste : 0.0f;
    float s1e = (st2e > 0.0f) ? ye / ste : 0.0f;
    float c1r = (st2r > 0.0f) ? xr / str : 0.0f;
    float s1r = (st2r > 0.0f) ? yr / str : 0.0f;

    float acc[7];
#pragma unroll
    for (int l = 0; l < 7; l++) acc[l] = 0.0f;

    float de = 0.28209479177387814f, dr = 0.28209479177387814f;
    float ce = 1.0f, se = 0.0f, cr = 1.0f, sr = 0.0f;
#pragma unroll
    for (int m = 0; m <= 6; m++) {
        if (m > 0) {
            float km = sqrtf((2.0f * m + 1.0f) / (2.0f * m));
            de = -km * ste * de;
            dr = -km * str * dr;
            float ce2 = c1e * ce - s1e * se; se = s1e * ce + c1e * se; ce = ce2;
            float cr2 = c1r * cr - s1r * sr; sr = s1r * cr + c1r * sr; cr = cr2;
        }
        float w = (m == 0) ? 1.0f : 2.0f * (ce * cr + se * sr);
        float pe1 = de, pr1 = dr;
        acc[m] += w * pe1 * pr1;
        if (m < 6) {
            float kp = sqrtf(2.0f * m + 3.0f);
            float pe = kp * ze * de;
            float pr = kp * zr * dr;
            acc[m + 1] += w * pe * pr;
            float pe0 = pe1, pr0 = pr1;
#pragma unroll
            for (int l = m + 2; l <= 6; l++) {
                float fl = (float)l;
                float a = sqrtf((4.0f * fl * fl - 1.0f) / (fl * fl - (float)(m * m)));
                float b = sqrtf(((fl - 1.0f) * (fl - 1.0f) - (float)(m * m)) /
                                (4.0f * (fl - 1.0f) * (fl - 1.0f) - 1.0f));
                float pen = a * (ze * pe - b * pe0); pe0 = pe; pe = pen;
                float prn = a * (zr * pr - b * pr0); pr0 = pr; pr = prn;
                acc[l] += w * pe * pr;
            }
        }
    }
    const float fourpi = 12.566370614359172f;
#pragma unroll
    for (int l = 0; l < 7; l++) inv[l] = acc[l] * (fourpi / (2.0f * l + 1.0f));
}

// ====== kernel 3: fused pre-work — roles by block range (all independent) ======
#define GB 1563
#define SB 888
#define ZB 400

__global__ void __launch_bounds__(256)
k_pre(const float* __restrict__ ud, const int* __restrict__ eidx,
      const float* __restrict__ ln_g, const float* __restrict__ ln_b,
      const float* __restrict__ ns, const float* __restrict__ W1,
      const float* __restrict__ b1, const float* __restrict__ W2,
      const float* __restrict__ b2,
      float4* __restrict__ out4, int n_out4, int N, int E) {
    __shared__ float sW1[64 * 32];
    __shared__ float sW2[32 * 192];
    int tid = threadIdx.x;
    int bid = blockIdx.x;

    if (bid < GB) {
        // ---------------- geom role (ref-vec normalize folded in) ----------
        int e = bid * 256 + tid;
        if (e >= E) return;
        float ux = ud[e * 3 + 0], uy = ud[e * 3 + 1], uz = ud[e * 3 + 2];
        int i = __ldg(&eidx[E + e]);
        float4 a = *(const float4*)&g_ref_accum[i * 4];
        float ic = 1.0f / fmaxf(a.w, 1.0f);
        float rx = a.x * ic, ry = a.y * ic, rz = a.z * ic;
        float norm = sqrtf(rx * rx + ry * ry + rz * rz + 1e-9f);
        float inm = 1.0f / norm;
        rx *= inm; ry *= inm; rz *= inm;
        if (norm < 5e-5f) { rx = 1.0f; ry = 0.0f; rz = 0.0f; }

        float inv[7];
        sh_invariants(ux, uy, uz, rx, ry, rz, inv);
        float mu = 0.0f;
#pragma unroll
        for (int l = 0; l < 7; l++) mu += inv[l];
        mu *= (1.0f / 7.0f);
        float var = 0.0f;
#pragma unroll
        for (int l = 0; l < 7; l++) { float d = inv[l] - mu; var += d * d; }
        var *= (1.0f / 7.0f);
        float isd = rsqrtf(var + 1e-5f);
        float o[8];
        o[0] = ux * rx + uy * ry + uz * rz;
#pragma unroll
        for (int l = 0; l < 7; l++)
            o[1 + l] = (inv[l] - mu) * isd * ln_g[l] + ln_b[l];
        float4* gg = (float4*)(g_geom + (size_t)e * 8);
        gg[0] = make_float4(o[0], o[1], o[2], o[3]);
        gg[1] = make_float4(o[4], o[5], o[6], o[7]);
        return;
    }
    if (bid >= GB + SB) {
        // ---------------- zero-out role ----------------
        int zb = bid - GB - SB;
        float4 z = make_float4(0.f, 0.f, 0.f, 0.f);
        for (int i = zb * 256 + tid; i < n_out4; i += ZB * 256) out4[i] = z;
        return;
    }

    // ---------------- sproj role (fp16 output) ----------------
    int sbid = bid - GB;
    for (int q = tid; q < 64 * 32; q += 256) sW1[q] = W1[q];
    for (int q = tid; q < 32 * 192; q += 256) sW2[q] = W2[q];
    __syncthreads();
    const u64* sW2u = (const u64*)sW2;
    const float2* b2p = (const float2*)b2;
    int lane = tid & 31, warp = tid >> 5;

    u64 bb[3];
#pragma unroll
    for (int k = 0; k < 3; k++) {
        float2 t = b2p[lane + 32 * k];
        bb[k] = pk2(t.x, t.y);
    }
    float b1v = b1[lane];

    int npairs = (N + 1) >> 1;
    for (int p = sbid * 8 + warp; p < npairs; p += SB * 8) {
        int nA = p * 2;
        int nB = min(nA + 1, N - 1);
        float aA0 = ns[(size_t)nA * 64 + lane], aA1 = ns[(size_t)nA * 64 + 32 + lane];
        float aB0 = ns[(size_t)nB * 64 + lane], aB1 = ns[(size_t)nB * 64 + 32 + lane];
        float tA = b1v, tB = b1v;
#pragma unroll
        for (int r = 0; r < 64; r++) {
            float w = sW1[r * 32 + lane];
            float vA = __shfl_sync(0xffffffffu, (r < 32) ? aA0 : aA1, r & 31);
            float vB = __shfl_sync(0xffffffffu, (r < 32) ? aB0 : aB1, r & 31);
            tA = fmaf(vA, w, tA);
            tB = fmaf(vB, w, tB);
        }
        tA = __fdividef(tA, 1.0f + __expf(-tA)) * (1.0f / 0.6f);
        tB = __fdividef(tB, 1.0f + __expf(-tB)) * (1.0f / 0.6f);
        u64 oA[3], oB[3];
#pragma unroll
        for (int k = 0; k < 3; k++) { oA[k] = bb[k]; oB[k] = bb[k]; }
#pragma unroll
        for (int r = 0; r < 32; r++) {
            u64 w0 = sW2u[r * 96 + lane];
            u64 w1 = sW2u[r * 96 + 32 + lane];
            u64 w2 = sW2u[r * 96 + 64 + lane];
            float vA = __shfl_sync(0xffffffffu, tA, r);
            float vB = __shfl_sync(0xffffffffu, tB, r);
            u64 vvA = pk2(vA, vA), vvB = pk2(vB, vB);
            oA[0] = ffma2(vvA, w0, oA[0]);
            oA[1] = ffma2(vvA, w1, oA[1]);
            oA[2] = ffma2(vvA, w2, oA[2]);
            oB[0] = ffma2(vvB, w0, oB[0]);
            oB[1] = ffma2(vvB, w1, oB[1]);
            oB[2] = ffma2(vvB, w2, oB[2]);
        }
        __half2* outA = g_sproj_h + (size_t)nA * 96;
#pragma unroll
        for (int k = 0; k < 3; k++) {
            float lo, hi; upk2(oA[k], lo, hi);
            outA[lane + 32 * k] = __floats2half2_rn(lo, hi);
        }
        if (nB != nA) {
            __half2* outB = g_sproj_h + (size_t)nB * 96;
#pragma unroll
            for (int k = 0; k < 3; k++) {
                float lo, hi; upk2(oB[k], lo, hi);
                outB[lane + 32 * k] = __floats2half2_rn(lo, hi);
            }
        }
    }
}

// ====== kernel 4: fp16 MMA GEMM + tensor-core gate + fused epilogue ======
// Persistent CTAs (3/SM), 256 threads = 8 warps (4 m-warps x 2 n-warps).
// Tile: 64 edges x 192 cols, K = 64 (4 chunks of k16). Warp: 16 x 96,
// processed as 2 halves of 6 n-blocks. Gate held packed fp16 (12 regs).
#define HS 72   // half stride per row (A and B smem)

__global__ void __launch_bounds__(256, 3)
k_gemm(const float* __restrict__ rbf, const int* __restrict__ eidx,
       const float* __restrict__ W_edge, const float* __restrict__ b_edge,
       const float* __restrict__ W_inv, const float* __restrict__ b_inv,
       int E) {
    extern __shared__ float sm[];
    __half* sBh  = (__half*)sm;             // 192*HS (W_edge^T, k contig)
    __half* sAh  = sBh + 192 * HS;          // 64*HS  (rbf tile)
    __half* sWih = sAh + 64 * HS;           // 192*8  (W_inv, n-major k contig)
    __half* sGh  = sWih + 192 * 8;          // 64*8   (geom tile)
    float* sBe = (float*)(sGh + 64 * 8);    // 192
    float* sBi = sBe + 192;                 // 192
    int*   sJ  = (int*)(sBi + 192);         // 64

    int tid = threadIdx.x;
    int lane = tid & 31, warp = tid >> 5;
    int wm = warp >> 1, wn = warp & 1;
    int gid = lane >> 2, tig = lane & 3;

    // persistent staging: W_edge^T (fp16), W_inv (fp16 fragment layout), biases
    for (int i = tid; i < 64 * 192; i += 256) {
        int k = i / 192, n = i - k * 192;
        sBh[n * HS + k] = __float2half_rn(W_edge[i]);
    }
    for (int i = tid; i < 8 * 192; i += 256) {
        int q = i / 192, n = i - q * 192;
        sWih[n * 8 + q] = __float2half_rn(W_inv[i]);
    }
    if (tid < 192) { sBe[tid] = b_edge[tid]; sBi[tid] = b_inv[tid]; }

    const float2* sBe2 = (const float2*)sBe;
    const float2* sBi2 = (const float2*)sBi;

    int r0 = wm * 16 + gid;
    int nb_base = wn * 96;
    const float inv_sqrt3 = 0.57735026918962576f;

    int ntiles = (E + GTE - 1) / GTE;
    for (int t = blockIdx.x; t < ntiles; t += gridDim.x) {
        int e0 = t * GTE;
        __syncthreads();  // staging buffers free (also covers first-iter staging)

        // stage A tile (f32 -> fp16)
        for (int i = tid; i < 64 * 8; i += 256) {
            int r = i >> 3, c8 = i & 7;
            int e = min(e0 + r, E - 1);
            const float4* src = (const float4*)(rbf + (size_t)e * 64 + c8 * 8);
            float4 v0 = __ldg(src);
            float4 v1 = __ldg(src + 1);
            uint4 u;
            u.x = f2h2(v0.x, v0.y);
            u.y = f2h2(v0.z, v0.w);
            u.z = f2h2(v1.x, v1.y);
            u.w = f2h2(v1.z, v1.w);
            *(uint4*)(sAh + r * HS + c8 * 8) = u;
        }
        // stage geom (fp16) + j-index
        if (tid < 64) {
            int e = min(e0 + tid, E - 1);
            const float4* gp = (const float4*)(g_geom + (size_t)e * 8);
            float4 v0 = __ldg(gp), v1 = __ldg(gp + 1);
            uint4 u;
            u.x = f2h2(v0.x, v0.y);
            u.y = f2h2(v0.z, v0.w);
            u.z = f2h2(v1.x, v1.y);
            u.w = f2h2(v1.z, v1.w);
            *(uint4*)(sGh + tid * 8) = u;
            sJ[tid] = __ldg(&eidx[e]);
        }
        __syncthreads();

        int j0 = sJ[r0], j1 = sJ[r0 + 8];
        bool val0 = (e0 + r0) < E, val1 = (e0 + r0 + 8) < E;
        __half* xrow0 = g_x + (size_t)(e0 + r0) * 192;
        __half* xrow1 = g_x + (size_t)(e0 + r0 + 8) * 192;

        uint32_t ga0 = *(const uint32_t*)(sGh + r0 * 8 + tig * 2);
        uint32_t ga1 = *(const uint32_t*)(sGh + (r0 + 8) * 8 + tig * 2);

#pragma unroll
        for (int h = 0; h < 2; h++) {
            int nbh = nb_base + h * 48;
            float acc[6][4];
            __half2 gate[6][2];  // packed: [0]=(c0,c1) row r0, [1]=(c2,c3) row r0+8

            // ---- gate MMA (k8): gacc = geom @ W_inv ----
#pragma unroll
            for (int nb = 0; nb < 6; nb++)
                acc[nb][0] = acc[nb][1] = acc[nb][2] = acc[nb][3] = 0.0f;
#pragma unroll
            for (int nb = 0; nb < 6; nb++) {
                int n = nbh + nb * 8 + gid;
                uint32_t b0 = *(const uint32_t*)(sWih + n * 8 + tig * 2);
                mma_f16_k8(acc[nb], ga0, ga1, b0);
            }
#pragma unroll
            for (int nb = 0; nb < 6; nb++) {
                int ch = (nbh + nb * 8 + tig * 2) >> 1;
                float2 bi = sBi2[ch];
                gate[nb][0] = __floats2half2_rn(gatef(acc[nb][0] + bi.x),
                                                gatef(acc[nb][1] + bi.y));
                gate[nb][1] = __floats2half2_rn(gatef(acc[nb][2] + bi.x),
                                                gatef(acc[nb][3] + bi.y));
                acc[nb][0] = acc[nb][1] = acc[nb][2] = acc[nb][3] = 0.0f;
            }

            // ---- main MMA (4 k16-chunks) ----
#pragma unroll
            for (int kc = 0; kc < 4; kc++) {
                int kb = kc * 16 + tig * 2;
                uint32_t a0 = *(const uint32_t*)(sAh + r0 * HS + kb);
                uint32_t a1 = *(const uint32_t*)(sAh + (r0 + 8) * HS + kb);
                uint32_t a2 = *(const uint32_t*)(sAh + r0 * HS + kb + 8);
                uint32_t a3 = *(const uint32_t*)(sAh + (r0 + 8) * HS + kb + 8);
#pragma unroll
                for (int nb = 0; nb < 6; nb++) {
                    int n = nbh + nb * 8 + gid;
                    uint32_t b0 = *(const uint32_t*)(sBh + n * HS + kb);
                    uint32_t b1 = *(const uint32_t*)(sBh + n * HS + kb + 8);
                    mma_f16(acc[nb], a0, a1, a2, a3, b0, b1);
                }
            }

            // ---- epilogue: bias + gate + sproj -> g_x (fp16) ----
#pragma unroll
            for (int nb = 0; nb < 6; nb++) {
                int col = nbh + nb * 8 + tig * 2;
                int ch = col >> 1;
                float2 be = sBe2[ch];
                float2 g0 = __half22float2(gate[nb][0]);
                float2 g1 = __half22float2(gate[nb][1]);
                float2 sp0 = __half22float2(__ldg(&g_sproj_h[(size_t)j0 * 96 + ch]));
                float2 sp1 = __half22float2(__ldg(&g_sproj_h[(size_t)j1 * 96 + ch]));
                float x00 = sp0.x * (acc[nb][0] + be.x) * g0.x * inv_sqrt3;
                float x01 = sp0.y * (acc[nb][1] + be.y) * g0.y * inv_sqrt3;
                float x10 = sp1.x * (acc[nb][2] + be.x) * g1.x * inv_sqrt3;
                float x11 = sp1.y * (acc[nb][3] + be.y) * g1.y * inv_sqrt3;
                if (val0) *(__half2*)(xrow0 + col) = __floats2half2_rn(x00, x01);
                if (val1) *(__half2*)(xrow1 + col) = __floats2half2_rn(x10, x11);
            }
        }
    }
}

// ================= kernel 5: scatter (warp per edge) =================
__global__ void __launch_bounds__(256)
k_scatter(const float* __restrict__ ud, const int* __restrict__ eidx,
          const float* __restrict__ nv, float* __restrict__ out, int N, int E) {
    __shared__ __align__(16) float sX[8][192];
    int lane = threadIdx.x & 31, warp = threadIdx.x >> 5;
    float* xf = sX[warp];
    float* outv = out + (size_t)N * 64;
    const float ish = 0.125f;

    for (int e = blockIdx.x * 8 + warp; e < E; e += gridDim.x * 8) {
        const __half2* xr = (const __half2*)(g_x + (size_t)e * 192);
        float2 v0 = __half22float2(__ldg(xr + lane));        // x1
        float2 v1 = __half22float2(__ldg(xr + 32 + lane));   // x2
        float2 v2 = __half22float2(__ldg(xr + 64 + lane));   // x3
        ((float2*)xf)[lane] = v0;
        ((float2*)xf)[32 + lane] = v1;
        ((float2*)xf)[64 + lane] = v2;
        int j = __ldg(&eidx[e]), in = __ldg(&eidx[E + e]);
        float ud0 = __ldg(&ud[e * 3 + 0]);
        float ud1 = __ldg(&ud[e * 3 + 1]);
        float ud2 = __ldg(&ud[e * 3 + 2]);
        __syncwarp();

        if (lane < 16) {  // delta_scalar: x3
            const float4 x3v = *(const float4*)&xf[128 + 4 * lane];
            red4(&out[(size_t)in * 64 + 4 * lane], x3v.x, x3v.y, x3v.z, x3v.w);
        }
        {  // delta_vector d=0,1: o = 4*lane in [0,128)
            int o = 4 * lane;
            float udd = (o >> 6) ? ud1 : ud0;
            int h = o & 63;
            const float4 f1 = *(const float4*)&xf[h];
            const float4 f2 = *(const float4*)&xf[64 + h];
            float4 nvv = __ldg((const float4*)(nv + (size_t)j * 192 + o));
            red4(&outv[(size_t)in * 192 + o],
                 (f1.x * nvv.x + f2.x * udd) * ish,
                 (f1.y * nvv.y + f2.y * udd) * ish,
                 (f1.z * nvv.z + f2.z * udd) * ish,
                 (f1.w * nvv.w + f2.w * udd) * ish);
        }
        if (lane < 16) {  // delta_vector d=2
            int o = 128 + 4 * lane;
            int h = 4 * lane;
            const float4 f1 = *(const float4*)&xf[h];
            const float4 f2 = *(const float4*)&xf[64 + h];
            float4 nvv = __ldg((const float4*)(nv + (size_t)j * 192 + o));
            red4(&outv[(size_t)in * 192 + o],
                 (f1.x * nvv.x + f2.x * ud2) * ish,
                 (f1.y * nvv.y + f2.y * ud2) * ish,
                 (f1.z * nvv.z + f2.z * ud2) * ish,
                 (f1.w * nvv.w + f2.w * ud2) * ish);
        }
        __syncwarp();
    }
}

// ================= launch =================
extern "C" void kernel_launch(void* const* d_in, const int* in_sizes, int n_in,
                              void* d_out, int out_size) {
    const float* node_scalar = (const float*)d_in[0];
    const float* node_vector = (const float*)d_in[1];
    const float* edge_rbf    = (const float*)d_in[2];
    const float* edge_udiff  = (const float*)d_in[3];
    const int*   edge_index  = (const int*)d_in[4];
    const float* W_edge      = (const float*)d_in[5];
    const float* b_edge      = (const float*)d_in[6];
    const float* W_x1        = (const float*)d_in[7];
    const float* b_x1        = (const float*)d_in[8];
    const float* W_x2        = (const float*)d_in[9];
    const float* b_x2        = (const float*)d_in[10];
    const float* ln_g        = (const float*)d_in[11];
    const float* ln_b        = (const float*)d_in[12];
    const float* W_inv       = (const float*)d_in[13];
    const float* b_inv       = (const float*)d_in[14];

    int N = in_sizes[0] / 64;
    int E = in_sizes[3] / 3;
    float* out = (float*)d_out;

    // dynamic smem for k_gemm: Bh + Ah + Wih + Gh (halves) + biases + J
    int smem_gemm = (192 * HS + 64 * HS + 192 * 8 + 64 * 8) * 2
                    + (192 + 192) * 4 + 64 * 4;
    cudaFuncSetAttribute(k_gemm, cudaFuncAttributeMaxDynamicSharedMemorySize,
                         smem_gemm);

    k_zacc<<<(N + 255) / 256, 256>>>(N);  // N float4 accumulators
    k_refaccum<<<(E + 255) / 256, 256>>>(edge_udiff, edge_index, E);
    // fused independent pre-work: geom (incl. refvec) + sproj + zero-out
    k_pre<<<GB + SB + ZB, 256>>>(edge_udiff, edge_index, ln_g, ln_b,
                                 node_scalar, W_x1, b_x1, W_x2, b_x2,
                                 (float4*)out, out_size / 4, N, E);
    k_gemm<<<444, 256, smem_gemm>>>(edge_rbf, edge_index, W_edge, b_edge,
                                    W_inv, b_inv, E);
    k_scatter<<<2960, 256>>>(edge_udiff, edge_index, node_vector, out, N, E);
}